// round 15
// baseline (speedup 1.0000x reference)
#include <cuda_runtime.h>
#include <cuda_bf16.h>
#include <math.h>
#include <stdint.h>

#define D_    1024
#define B_    4
#define NTOK_ 8192
#define KG    64
#define BG_   512
#define E1_   8
#define S1_   2
#define M1_   16
#define HID_  4096
#define E2_   4
#define L2_   2048
#define N2_   512

// ---------------- fp32 scratch ----------------
__device__ float g_tscale[B_*NTOK_];
__device__ float g_gm[BG_*D_];
__device__ float g_gates[BG_];
__device__ float g_se[BG_*M1_*D_];
__device__ float g_combine[BG_*KG*M1_];
__device__ float g_h1[(size_t)B_*N2_*E2_*D_];          // se2_raw scratch
__device__ float g_seq[B_*L2_*D_];
__device__ float g_xs[B_*L2_*D_];
__device__ float g_cmean[B_*N2_*D_];
__device__ float g_logits2[(size_t)B_*L2_*L2_];
__device__ float g_logits2T[(size_t)B_*L2_*L2_];
__device__ float g_o2[B_*L2_*D_];
__device__ float g_out2[B_*L2_*D_];

// ---------------- pre-packed bf16 hi/lo weights, TRANSPOSED: H[n][k/2] ----------------
__device__ uint32_t g_Ws1h[(size_t)16384*512],      g_Ws1l[(size_t)16384*512];
__device__ uint32_t g_W1fh[(size_t)E1_*HID_*512],   g_W1fl[(size_t)E1_*HID_*512];
__device__ uint32_t g_W2fh[(size_t)E1_*D_*2048],    g_W2fl[(size_t)E1_*D_*2048];
__device__ uint32_t g_Ws2h[(size_t)4096*512],       g_Ws2l[(size_t)4096*512];
__device__ uint32_t g_W1sh[(size_t)E2_*HID_*512],   g_W1sl[(size_t)E2_*HID_*512];
__device__ uint32_t g_W2sh[(size_t)E2_*D_*2048],    g_W2sl[(size_t)E2_*D_*2048];

// ---------------- pre-packed activations (all GEMM A/B operands) ----------------
__device__ uint32_t g_gmH[512*512],                   g_gmL[512*512];
__device__ uint32_t g_cmH[2048*512],                  g_cmL[2048*512];
__device__ uint32_t g_xsH[(size_t)B_*L2_*512],        g_xsL[(size_t)B_*L2_*512];
__device__ uint32_t g_slH[(size_t)E1_*BG_*S1_*512],   g_slL[(size_t)E1_*BG_*S1_*512];
__device__ uint32_t g_s2H[(size_t)E2_*B_*N2_*512],    g_s2L[(size_t)E2_*B_*N2_*512];
__device__ uint32_t g_h1H[(size_t)8192*2048],         g_h1L[(size_t)8192*2048];
__device__ uint32_t g_se2H[(size_t)B_*L2_*512],       g_se2L[(size_t)B_*L2_*512];
__device__ uint32_t g_xsTH[(size_t)B_*D_*1024],       g_xsTL[(size_t)B_*D_*1024];
__device__ uint32_t g_o2TH[(size_t)B_*D_*1024],       g_o2TL[(size_t)B_*D_*1024];
__device__ uint32_t g_c2H[(size_t)B_*L2_*1024],       g_c2L[(size_t)B_*L2_*1024];
__device__ uint32_t g_dTH[(size_t)B_*L2_*1024],       g_dTL[(size_t)B_*L2_*1024];

// ---------------- helpers ----------------
__device__ __forceinline__ float gelu_exact(float x) {
    return 0.5f * x * (1.0f + erff(x * 0.70710678118654752440f));
}
__device__ __forceinline__ float blk_sum(float v, float* sm) {
    int t = threadIdx.x;
    sm[t] = v; __syncthreads();
    for (int s = 128; s > 0; s >>= 1) { if (t < s) sm[t] += sm[t + s]; __syncthreads(); }
    float r = sm[0]; __syncthreads(); return r;
}
__device__ __forceinline__ float blk_max(float v, float* sm) {
    int t = threadIdx.x;
    sm[t] = v; __syncthreads();
    for (int s = 128; s > 0; s >>= 1) { if (t < s) sm[t] = fmaxf(sm[t], sm[t + s]); __syncthreads(); }
    float r = sm[0]; __syncthreads(); return r;
}
__device__ __forceinline__ void packbf(float x, float y, uint32_t& h, uint32_t& l) {
    __nv_bfloat16 hx = __float2bfloat16(x), hy = __float2bfloat16(y);
    float rx = x - __bfloat162float(hx), ry = y - __bfloat162float(hy);
    h = ((uint32_t)__bfloat16_as_ushort(hy) << 16) | (uint32_t)__bfloat16_as_ushort(hx);
    l = ((uint32_t)__bfloat16_as_ushort(__float2bfloat16(ry)) << 16)
      | (uint32_t)__bfloat16_as_ushort(__float2bfloat16(rx));
}
__device__ __forceinline__ void mma16(float* c, const uint32_t* a, const uint32_t* b) {
    asm volatile(
        "mma.sync.aligned.m16n8k16.row.col.f32.bf16.bf16.f32 "
        "{%0,%1,%2,%3}, {%4,%5,%6,%7}, {%8,%9}, {%0,%1,%2,%3};"
        : "+f"(c[0]), "+f"(c[1]), "+f"(c[2]), "+f"(c[3])
        : "r"(a[0]), "r"(a[1]), "r"(a[2]), "r"(a[3]), "r"(b[0]), "r"(b[1]));
}
__device__ __forceinline__ void ldsm4(uint32_t& r0, uint32_t& r1, uint32_t& r2, uint32_t& r3,
                                      uint32_t addr) {
    asm volatile("ldmatrix.sync.aligned.m8n8.x4.shared.b16 {%0,%1,%2,%3}, [%4];"
                 : "=r"(r0), "=r"(r1), "=r"(r2), "=r"(r3) : "r"(addr));
}
__device__ __forceinline__ uint32_t smem_u32(const void* p) {
    uint32_t a;
    asm("{ .reg .u64 t; cvta.to.shared.u64 t, %1; cvt.u32.u64 %0, t; }" : "=r"(a) : "l"(p));
    return a;
}

// weight/act pre-pack TRANSPOSED: W[k][n] f32 -> H/L[n][k/2]
__global__ void convwT_k(const float* __restrict__ W, uint32_t* __restrict__ H,
                         uint32_t* __restrict__ Lo, int N, int Kd) {
    __shared__ uint32_t th[32][33], tl[32][33];
    int Kd2 = Kd >> 1;
    size_t zW = (size_t)blockIdx.z * Kd * N;
    size_t zH = (size_t)blockIdx.z * (size_t)Kd2 * N;
    int n0 = blockIdx.x * 32, kp0 = blockIdx.y * 32;
    int tx = threadIdx.x, ty = threadIdx.y;
    #pragma unroll
    for (int r = 0; r < 4; r++) {
        int kpl = ty + 8 * r;
        int k = (kp0 + kpl) * 2;
        float v0 = W[zW + (size_t)k * N + n0 + tx];
        float v1 = W[zW + (size_t)(k + 1) * N + n0 + tx];
        packbf(v0, v1, th[kpl][tx], tl[kpl][tx]);
    }
    __syncthreads();
    #pragma unroll
    for (int r = 0; r < 4; r++) {
        int n = ty + 8 * r;
        size_t o = zH + (size_t)(n0 + n) * Kd2 + kp0 + tx;
        H[o] = th[tx][n];
        Lo[o] = tl[tx][n];
    }
}

// row-major pack: fp32 -> H/L (k-pairs along last dim)
__global__ void packrow_k(const float* __restrict__ in, uint32_t* __restrict__ H,
                          uint32_t* __restrict__ L) {
    size_t i = (size_t)blockIdx.x * 256 + threadIdx.x;
    float4 v = ((const float4*)in)[i];
    uint32_t h0, l0, h1, l1;
    packbf(v.x, v.y, h0, l0);
    packbf(v.z, v.w, h1, l1);
    uint2 hh; hh.x = h0; hh.y = h1;
    uint2 ll; ll.x = l0; ll.y = l1;
    ((uint2*)H)[i] = hh;
    ((uint2*)L)[i] = ll;
}

// ---------------- small kernels ----------------
__global__ void token_scale_k(const float* __restrict__ x) {
    int row = blockIdx.x;
    const float* p = x + (size_t)row * D_;
    float ss = 0.f;
    for (int d = threadIdx.x; d < D_; d += 256) { float v = p[d]; ss += v * v; }
    __shared__ float sm[256];
    float tot = blk_sum(ss, sm);
    if (threadIdx.x == 0) g_tscale[row] = 32.0f / fmaxf(sqrtf(tot), 1e-8f);
}
__global__ void group_mean_k(const float* __restrict__ x) {
    int bg = blockIdx.x;
    size_t base = (size_t)bg * KG * D_;
    for (int d = threadIdx.x; d < D_; d += 256) {
        float s = 0.f;
        for (int k = 0; k < KG; k++) s += x[base + (size_t)k * D_ + d];
        g_gm[(size_t)bg * D_ + d] = s * (1.0f / KG);
    }
}
__global__ void gates_k(const float* __restrict__ Wg, const float* __restrict__ bgb) {
    int bg = blockIdx.x;
    float s = 0.f;
    for (int d = threadIdx.x; d < D_; d += 256) s += g_gm[(size_t)bg * D_ + d] * Wg[d];
    __shared__ float sm[256];
    float tot = blk_sum(s, sm);
    if (threadIdx.x == 0) {
        float v = 1.0f / (1.0f + expf(-(tot + bgb[0])));
        g_gates[bg] = fminf(fmaxf(v, 0.01f), 1.0f);
    }
}
__global__ void slot_norm_k(const float* __restrict__ gs1, const float* __restrict__ g1) {
    int row = blockIdx.x;
    float* p = g_se + (size_t)row * D_;
    float ss = 0.f;
    for (int d = threadIdx.x; d < D_; d += 256) { float v = p[d]; ss += v * v; }
    __shared__ float sm[256];
    float tot = blk_sum(ss, sm);
    float sc = 32.0f / fmaxf(sqrtf(tot), 1e-8f);
    for (int d = threadIdx.x; d < D_; d += 256)
        p[d] = p[d] * sc * gs1[d] * g1[d];
}
__global__ void xs_norm_k(const float* __restrict__ g2) {
    int row = blockIdx.x;
    const float* p = g_seq + (size_t)row * D_;
    float ss = 0.f;
    for (int d = threadIdx.x; d < D_; d += 256) { float v = p[d]; ss += v * v; }
    __shared__ float sm[256];
    float tot = blk_sum(ss, sm);
    float sc = 32.0f / fmaxf(sqrtf(tot), 1e-8f);
    float* o = g_xs + (size_t)row * D_;
    for (int d = threadIdx.x; d < D_; d += 256)
        o[d] = p[d] * sc * g2[d];
}
__global__ void cmean_k() {
    int r = blockIdx.x;
    size_t base = (size_t)r * 4 * D_;
    for (int d = threadIdx.x; d < D_; d += 256) {
        float s = g_xs[base + d] + g_xs[base + D_ + d] + g_xs[base + 2*D_ + d] + g_xs[base + 3*D_ + d];
        g_cmean[(size_t)r * D_ + d] = s * 0.25f;
    }
}
// se2 norm, writes PACKED rows directly
__global__ void se2_normpack_k(const float* __restrict__ gs2,
                               uint32_t* __restrict__ H, uint32_t* __restrict__ L) {
    int bid = blockIdx.x;
    int r = bid >> 2, e = bid & 3;
    const float* in = g_h1 + (size_t)r * (E2_ * D_) + (size_t)e * D_;
    int t = threadIdx.x;
    float2 v0 = ((const float2*)in)[t];
    float2 v1 = ((const float2*)in)[t + 256];
    float ss = v0.x * v0.x + v0.y * v0.y + v1.x * v1.x + v1.y * v1.y;
    __shared__ float sm[256];
    float tot = blk_sum(ss, sm);
    float sc = 32.0f / fmaxf(sqrtf(tot), 1e-8f);
    int b = r >> 9, n = r & 511;
    size_t row = (size_t)b * L2_ + (size_t)e * N2_ + n;
    uint32_t h, l;
    packbf(v0.x * sc * gs2[2*t],     v0.y * sc * gs2[2*t+1],     h, l);
    H[row * 512 + t] = h; L[row * 512 + t] = l;
    packbf(v1.x * sc * gs2[2*t+512], v1.y * sc * gs2[2*t+513],   h, l);
    H[row * 512 + t + 256] = h; L[row * 512 + t + 256] = l;
}

// ---------------- fused group attention (slots written PACKED, coalesced) ----------------
__global__ void __launch_bounds__(256) group_attn_k(const float* __restrict__ x) {
    int bg = blockIdx.x;
    int tid = threadIdx.x;
    __shared__ float xs_sm[64][65];
    __shared__ float se_sm[16][65];
    __shared__ float comb_sm[64][17];
    const float* xbase  = x + (size_t)bg * KG * D_;
    const float* sebase = g_se + (size_t)bg * M1_ * D_;
    int k = tid >> 2, q = tid & 3;
    float acc0 = 0.f, acc1 = 0.f, acc2 = 0.f, acc3 = 0.f;
    for (int c = 0; c < D_; c += 64) {
        #pragma unroll
        for (int i = 0; i < 4; i++) {
            int f = i * 256 + tid;
            int r = f >> 4, col = (f & 15) << 2;
            float4 v = *(const float4*)(xbase + (size_t)r * D_ + c + col);
            xs_sm[r][col] = v.x; xs_sm[r][col+1] = v.y; xs_sm[r][col+2] = v.z; xs_sm[r][col+3] = v.w;
        }
        {
            int r = tid >> 4, col = (tid & 15) << 2;
            float4 v = *(const float4*)(sebase + (size_t)r * D_ + c + col);
            se_sm[r][col] = v.x; se_sm[r][col+1] = v.y; se_sm[r][col+2] = v.z; se_sm[r][col+3] = v.w;
        }
        __syncthreads();
        #pragma unroll 8
        for (int dd = 0; dd < 64; dd++) {
            float xv = xs_sm[k][dd];
            acc0 = fmaf(xv, se_sm[q*4+0][dd], acc0);
            acc1 = fmaf(xv, se_sm[q*4+1][dd], acc1);
            acc2 = fmaf(xv, se_sm[q*4+2][dd], acc2);
            acc3 = fmaf(xv, se_sm[q*4+3][dd], acc3);
        }
        __syncthreads();
    }
    float s1v = g_tscale[bg * KG + k];
    acc0 *= s1v; acc1 *= s1v; acc2 *= s1v; acc3 *= s1v;
    float mx = fmaxf(fmaxf(acc0, acc1), fmaxf(acc2, acc3));
    mx = fmaxf(mx, __shfl_xor_sync(0xffffffffu, mx, 1));
    mx = fmaxf(mx, __shfl_xor_sync(0xffffffffu, mx, 2));
    float e0 = expf(acc0 - mx), e1 = expf(acc1 - mx), e2 = expf(acc2 - mx), e3 = expf(acc3 - mx);
    float s = e0 + e1 + e2 + e3;
    s += __shfl_xor_sync(0xffffffffu, s, 1);
    s += __shfl_xor_sync(0xffffffffu, s, 2);
    float inv = 1.0f / s;
    size_t cb = ((size_t)bg * KG + k) * M1_ + q * 4;
    comb_sm[k][q*4+0] = e0 * inv; g_combine[cb+0] = e0 * inv;
    comb_sm[k][q*4+1] = e1 * inv; g_combine[cb+1] = e1 * inv;
    comb_sm[k][q*4+2] = e2 * inv; g_combine[cb+2] = e2 * inv;
    comb_sm[k][q*4+3] = e3 * inv; g_combine[cb+3] = e3 * inv;
    __syncthreads();
    int m = tid >> 4, dq = tid & 15;
    for (int c = 0; c < D_; c += 64) {
        #pragma unroll
        for (int i = 0; i < 4; i++) {
            int f = i * 256 + tid;
            int r = f >> 4, col = (f & 15) << 2;
            float4 v = *(const float4*)(xbase + (size_t)r * D_ + c + col);
            xs_sm[r][col] = v.x; xs_sm[r][col+1] = v.y; xs_sm[r][col+2] = v.z; xs_sm[r][col+3] = v.w;
        }
        __syncthreads();
        float a0 = 0.f, a1 = 0.f, a2 = 0.f, a3 = 0.f;
        #pragma unroll 8
        for (int kk = 0; kk < 64; kk++) {
            float cv = comb_sm[kk][m];
            a0 = fmaf(cv, xs_sm[kk][dq*4+0], a0);
            a1 = fmaf(cv, xs_sm[kk][dq*4+1], a1);
            a2 = fmaf(cv, xs_sm[kk][dq*4+2], a2);
            a3 = fmaf(cv, xs_sm[kk][dq*4+3], a3);
        }
        int e = m >> 1, sl = m & 1;
        size_t rowi = (size_t)e * (BG_ * S1_) + bg * 2 + sl;
        uint32_t h0, l0, h1, l1;
        packbf(a0, a1, h0, l0);
        packbf(a2, a3, h1, l1);
        uint2 hh; hh.x = h0; hh.y = h1;
        uint2 ll; ll.x = l0; ll.y = l1;
        size_t po = rowi * 512 + ((c + dq * 4) >> 1);
        *(uint2*)(g_slH + po) = hh;
        *(uint2*)(g_slL + po) = ll;
        __syncthreads();
    }
}

// ======= bf16 split-3 tensor GEMM, 128x128 tile, Kc=16, ldmatrix, ALL operands pre-packed =======
// A: [M][K/2] hi/lo uint32 (lda in u32 units). B: [N][K/2] hi/lo uint32.
// EPI: 0 plain fp32; 1 bias+gelu -> PACKED (PH/PL); 2 ffn1-out fp32; 3 ffn2-out fp32;
//      4 slots2 -> PACKED remap; 5 plain + staged transposed copy (C2)
template<int EPI>
__global__ void __launch_bounds__(256, 2) tmma_k(
    const uint32_t* __restrict__ AH, const uint32_t* __restrict__ AL,
    const uint32_t* __restrict__ BH, const uint32_t* __restrict__ BL,
    float* __restrict__ C, float* __restrict__ C2,
    uint32_t* __restrict__ PH, uint32_t* __restrict__ PL,
    int Kd, int lda, int ldb, int ldc,
    size_t sA, size_t sB, size_t sC,
    const float* __restrict__ bias, int biasStride,
    const float* __restrict__ gvec, const float* __restrict__ evec)
{
    int z = blockIdx.z;
    AH += (size_t)z * sA; AL += (size_t)z * sA;
    BH += (size_t)z * sB; BL += (size_t)z * sB;

    __shared__ uint32_t Ah[2][128][12];
    __shared__ uint32_t Al[2][128][12];
    __shared__ uint32_t Bh[2][128][12];
    __shared__ uint32_t Bl[2][128][12];

    int tid = threadIdx.x;
    int lane = tid & 31, wid = tid >> 5;
    int g = lane >> 2, tig = lane & 3;
    int wm = wid >> 2, wn = wid & 3;
    int m0 = blockIdx.y * 128, n0 = blockIdx.x * 128;

    uint32_t AhB = smem_u32(&Ah[0][0][0]);
    uint32_t AlB = smem_u32(&Al[0][0][0]);
    uint32_t BhB = smem_u32(&Bh[0][0][0]);
    uint32_t BlB = smem_u32(&Bl[0][0][0]);
    uint32_t aAdd = (uint32_t)(wm * 64 + (lane & 15)) * 48u + (uint32_t)(lane >> 4) * 16u;
    uint32_t bAdd = (uint32_t)(wn * 32 + (lane & 7) + ((lane >> 4) << 3)) * 48u
                  + (uint32_t)((lane >> 3) & 1) * 16u;

    float acc[4][4][4];
    #pragma unroll
    for (int i = 0; i < 4; i++)
        #pragma unroll
        for (int j = 0; j < 4; j++)
            #pragma unroll
            for (int r = 0; r < 4; r++) acc[i][j][r] = 0.f;

    int nChunks = Kd >> 4;
    uint4 pah, pal, pbh, pbl;

    #define LOAD_CHUNK(k0) do {                                                                      \
        size_t offA = (size_t)(m0 + (tid >> 1)) * lda + ((k0) >> 1) + (tid & 1) * 4;                 \
        pah = *(const uint4*)(AH + offA); pal = *(const uint4*)(AL + offA);                          \
        size_t offB = (size_t)(n0 + (tid >> 1)) * ldb + ((k0) >> 1) + (tid & 1) * 4;                 \
        pbh = *(const uint4*)(BH + offB); pbl = *(const uint4*)(BL + offB);                          \
    } while (0)

    #define STORE_CHUNK(buf) do {                                                                   \
        int mm = tid >> 1, w0 = (tid & 1) * 4;                                                       \
        *(uint4*)&Ah[buf][mm][w0] = pah; *(uint4*)&Al[buf][mm][w0] = pal;                            \
        *(uint4*)&Bh[buf][mm][w0] = pbh; *(uint4*)&Bl[buf][mm][w0] = pbl;                            \
    } while (0)

    LOAD_CHUNK(0);
    STORE_CHUNK(0);
    __syncthreads();

    for (int t = 0; t < nChunks; t++) {
        int cur = t & 1;
        uint32_t cb = (uint32_t)cur * (128u * 48u);
        if (t + 1 < nChunks) LOAD_CHUNK((t + 1) * 16);

        uint32_t bh[4][2], bl[4][2];
        #pragma unroll
        for (int jj = 0; jj < 2; jj++) {
            ldsm4(bh[2*jj][0], bh[2*jj][1], bh[2*jj+1][0], bh[2*jj+1][1],
                  BhB + cb + bAdd + (uint32_t)jj * 16u * 48u);
            ldsm4(bl[2*jj][0], bl[2*jj][1], bl[2*jj+1][0], bl[2*jj+1][1],
                  BlB + cb + bAdd + (uint32_t)jj * 16u * 48u);
        }
        #pragma unroll
        for (int i = 0; i < 4; i++) {
            uint32_t ah[4], al[4];
            ldsm4(ah[0], ah[1], ah[2], ah[3], AhB + cb + aAdd + (uint32_t)i * 16u * 48u);
            ldsm4(al[0], al[1], al[2], al[3], AlB + cb + aAdd + (uint32_t)i * 16u * 48u);
            #pragma unroll
            for (int j = 0; j < 4; j++) {
                mma16(acc[i][j], al, bh[j]);
                mma16(acc[i][j], ah, bl[j]);
                mma16(acc[i][j], ah, bh[j]);
            }
        }

        if (t + 1 < nChunks) STORE_CHUNK((t + 1) & 1);
        __syncthreads();
    }
    #undef LOAD_CHUNK
    #undef STORE_CHUNK

    #pragma unroll
    for (int i = 0; i < 4; i++) {
        #pragma unroll
        for (int j = 0; j < 4; j++) {
            #pragma unroll
            for (int rr = 0; rr < 2; rr++) {
                int m = m0 + wm * 64 + 16 * i + g + rr * 8;
                int n = n0 + wn * 32 + 8 * j + 2 * tig;
                float v0 = acc[i][j][rr * 2 + 0];
                float v1 = acc[i][j][rr * 2 + 1];
                if (EPI == 0) {
                    float2 vv; vv.x = v0; vv.y = v1;
                    *(float2*)(C + (size_t)z * sC + (size_t)m * ldc + n) = vv;
                } else if (EPI == 1) {
                    v0 = gelu_exact(v0 + bias[(size_t)z * biasStride + n]);
                    v1 = gelu_exact(v1 + bias[(size_t)z * biasStride + n + 1]);
                    uint32_t h, l;
                    packbf(v0, v1, h, l);
                    size_t o = (size_t)z * sC + (size_t)m * (ldc >> 1) + (n >> 1);
                    PH[o] = h; PL[o] = l;
                } else if (EPI == 2) {
                    int e = z;
                    int row = (m >> 1) * M1_ + e * S1_ + (m & 1);
                    float sc = evec[e] * gvec[m >> 1];
                    float2 vv;
                    vv.x = (v0 + bias[(size_t)e * biasStride + n]) * sc;
                    vv.y = (v1 + bias[(size_t)e * biasStride + n + 1]) * sc;
                    *(float2*)(C + (size_t)row * ldc + n) = vv;
                } else if (EPI == 3) {
                    int e = z;
                    int row = (m >> 9) * L2_ + e * N2_ + (m & 511);
                    float2 vv;
                    vv.x = v0 + bias[(size_t)e * biasStride + n];
                    vv.y = v1 + bias[(size_t)e * biasStride + n + 1];
                    *(float2*)(C + (size_t)row * ldc + n) = vv;
                } else if (EPI == 4) {
                    int row = ((m >> 9) * B_ + z) * N2_ + (m & 511);
                    uint32_t h, l;
                    packbf(v0, v1, h, l);
                    size_t o = (size_t)row * (ldc >> 1) + (n >> 1);
                    PH[o] = h; PL[o] = l;
                } else { // EPI == 5: plain row-major part
                    float2 vv; vv.x = v0; vv.y = v1;
                    *(float2*)(C + (size_t)z * sC + (size_t)m * ldc + n) = vv;
                }
            }
        }
    }

    // EPI == 5: SMEM-staged coalesced transposed copy to C2
    if (EPI == 5) {
        float* tsm = (float*)&Ah[0][0][0] + (size_t)wid * 288;
        float* t2 = C2 + (size_t)z * sC;
        #pragma unroll
        for (int i = 0; i < 4; i++) {
            #pragma unroll
            for (int rr = 0; rr < 2; rr++) {
                __syncwarp();
                #pragma unroll
                for (int j = 0; j < 4; j++) {
                    #pragma unroll
                    for (int c = 0; c < 2; c++) {
                        int nl = 8 * j + 2 * tig + c;
                        tsm[nl * 9 + g] = acc[i][j][rr * 2 + c];
                    }
                }
                __syncwarp();
                int n = n0 + wn * 32 + lane;
                int mb = m0 + wm * 64 + 16 * i + rr * 8;
                float4 w0, w1;
                w0.x = tsm[lane * 9 + 0]; w0.y = tsm[lane * 9 + 1];
                w0.z = tsm[lane * 9 + 2]; w0.w = tsm[lane * 9 + 3];
                w1.x = tsm[lane * 9 + 4]; w1.y = tsm[lane * 9 + 5];
                w1.z = tsm[lane * 9 + 6]; w1.w = tsm[lane * 9 + 7];
                *(float4*)(t2 + (size_t)n * ldc + mb) = w0;
                *(float4*)(t2 + (size_t)n * ldc + mb + 4) = w1;
            }
        }
    }
}

// ---------------- row softmax with fused bf16 hi/lo pack output ----------------
__global__ void rowsm_pack_k(const float* __restrict__ src,
                             uint32_t* __restrict__ H, uint32_t* __restrict__ L) {
    int row = blockIdx.x;
    int t = threadIdx.x;
    const float2* p = (const float2*)(src + (size_t)row * L2_);
    float2 v[4];
    float mx = -1e30f;
    #pragma unroll
    for (int i = 0; i < 4; i++) {
        v[i] = p[i * 256 + t];
        mx = fmaxf(mx, fmaxf(v[i].x, v[i].y));
    }
    __shared__ float sm[256];
    mx = blk_max(mx, sm);
    float ex[4][2];
    float s = 0.f;
    #pragma unroll
    for (int i = 0; i < 4; i++) {
        ex[i][0] = expf(v[i].x - mx);
        ex[i][1] = expf(v[i].y - mx);
        s += ex[i][0] + ex[i][1];
    }
    s = blk_sum(s, sm);
    float inv = 1.0f / s;
    #pragma unroll
    for (int i = 0; i < 4; i++) {
        uint32_t h, l;
        packbf(ex[i][0] * inv, ex[i][1] * inv, h, l);
        H[(size_t)row * 1024 + i * 256 + t] = h;
        L[(size_t)row * 1024 + i * 256 + t] = l;
    }
}

// ---------------- final recombination ----------------
__global__ void __launch_bounds__(256) final_k(float* __restrict__ out) {
    int bg = blockIdx.x;
    int tid = threadIdx.x;
    __shared__ float comb[64 * 16];
    __shared__ float o2sm[16 * 256];
    #pragma unroll
    for (int i = 0; i < 4; i++)
        comb[i * 256 + tid] = g_combine[(size_t)bg * 1024 + i * 256 + tid];
    for (int c = 0; c < D_; c += 256) {
        __syncthreads();
        #pragma unroll
        for (int i = 0; i < 4; i++) {
            int f = i * 256 + tid;
            int r = f >> 6, col = (f & 63) << 2;
            *(float4*)&o2sm[r * 256 + col] =
                *(const float4*)(g_out2 + ((size_t)bg * M1_ + r) * D_ + c + col);
        }
        __syncthreads();
        for (int k = 0; k < 64; k++) {
            float s = 0.f;
            #pragma unroll
            for (int m = 0; m < 16; m++)
                s = fmaf(comb[k * 16 + m], o2sm[m * 256 + tid], s);
            out[((size_t)bg * KG + k) * D_ + c + tid] = s;
        }
    }
}

// ---------------- launch ----------------
extern "C" void kernel_launch(void* const* d_in, const int* in_sizes, int n_in,
                              void* d_out, int out_size) {
    const float* x           = (const float*)d_in[0];
    const float* gamma1      = (const float*)d_in[1];
    const float* W_slot1     = (const float*)d_in[2];
    const float* gamma_slot1 = (const float*)d_in[3];
    const float* W1_first    = (const float*)d_in[4];
    const float* b1_first    = (const float*)d_in[5];
    const float* W2_first    = (const float*)d_in[6];
    const float* b2_first    = (const float*)d_in[7];
    const float* expert_g    = (const float*)d_in[8];
    const float* Wg          = (const float*)d_in[9];
    const float* bg_bias     = (const float*)d_in[10];
    const float* gamma2      = (const float*)d_in[11];
    const float* W_slot2     = (const float*)d_in[12];
    const float* gamma_slot2 = (const float*)d_in[13];
    const float* W1_second   = (const float*)d_in[14];
    const float* b1_second   = (const float*)d_in[15];
    const float* W2_second   = (const float*)d_in[16];
    const float* b2_second   = (const float*)d_in[17];
    float* out = (float*)d_out;

    float *p_gm, *p_se, *p_h1, *p_seq, *p_xs, *p_cmean,
          *p_logits2, *p_logits2T, *p_o2, *p_out2, *p_gates;
    uint32_t *pWs1h, *pWs1l, *pW1fh, *pW1fl, *pW2fh, *pW2fl,
             *pWs2h, *pWs2l, *pW1sh, *pW1sl, *pW2sh, *pW2sl;
    uint32_t *pgmH, *pgmL, *pcmH, *pcmL, *pxsH, *pxsL, *pslH, *pslL, *ps2H, *ps2L,
             *ph1H, *ph1L, *pse2H, *pse2L, *pxsTH, *pxsTL, *po2TH, *po2TL,
             *pc2H, *pc2L, *pdTH, *pdTL;
    cudaGetSymbolAddress((void**)&p_gm, g_gm);
    cudaGetSymbolAddress((void**)&p_gates, g_gates);
    cudaGetSymbolAddress((void**)&p_se, g_se);
    cudaGetSymbolAddress((void**)&p_h1, g_h1);
    cudaGetSymbolAddress((void**)&p_seq, g_seq);
    cudaGetSymbolAddress((void**)&p_xs, g_xs);
    cudaGetSymbolAddress((void**)&p_cmean, g_cmean);
    cudaGetSymbolAddress((void**)&p_logits2, g_logits2);
    cudaGetSymbolAddress((void**)&p_logits2T, g_logits2T);
    cudaGetSymbolAddress((void**)&p_o2, g_o2);
    cudaGetSymbolAddress((void**)&p_out2, g_out2);
    cudaGetSymbolAddress((void**)&pWs1h, g_Ws1h);
    cudaGetSymbolAddress((void**)&pWs1l, g_Ws1l);
    cudaGetSymbolAddress((void**)&pW1fh, g_W1fh);
    cudaGetSymbolAddress((void**)&pW1fl, g_W1fl);
    cudaGetSymbolAddress((void**)&pW2fh, g_W2fh);
    cudaGetSymbolAddress((void**)&pW2fl, g_W2fl);
    cudaGetSymbolAddress((void**)&pWs2h, g_Ws2h);
    cudaGetSymbolAddress((void**)&pWs2l, g_Ws2l);
    cudaGetSymbolAddress((void**)&pW1sh, g_W1sh);
    cudaGetSymbolAddress((void**)&pW1sl, g_W1sl);
    cudaGetSymbolAddress((void**)&pW2sh, g_W2sh);
    cudaGetSymbolAddress((void**)&pW2sl, g_W2sl);
    cudaGetSymbolAddress((void**)&pgmH, g_gmH);
    cudaGetSymbolAddress((void**)&pgmL, g_gmL);
    cudaGetSymbolAddress((void**)&pcmH, g_cmH);
    cudaGetSymbolAddress((void**)&pcmL, g_cmL);
    cudaGetSymbolAddress((void**)&pxsH, g_xsH);
    cudaGetSymbolAddress((void**)&pxsL, g_xsL);
    cudaGetSymbolAddress((void**)&pslH, g_slH);
    cudaGetSymbolAddress((void**)&pslL, g_slL);
    cudaGetSymbolAddress((void**)&ps2H, g_s2H);
    cudaGetSymbolAddress((void**)&ps2L, g_s2L);
    cudaGetSymbolAddress((void**)&ph1H, g_h1H);
    cudaGetSymbolAddress((void**)&ph1L, g_h1L);
    cudaGetSymbolAddress((void**)&pse2H, g_se2H);
    cudaGetSymbolAddress((void**)&pse2L, g_se2L);
    cudaGetSymbolAddress((void**)&pxsTH, g_xsTH);
    cudaGetSymbolAddress((void**)&pxsTL, g_xsTL);
    cudaGetSymbolAddress((void**)&po2TH, g_o2TH);
    cudaGetSymbolAddress((void**)&po2TL, g_o2TL);
    cudaGetSymbolAddress((void**)&pc2H, g_c2H);
    cudaGetSymbolAddress((void**)&pc2L, g_c2L);
    cudaGetSymbolAddress((void**)&pdTH, g_dTH);
    cudaGetSymbolAddress((void**)&pdTL, g_dTL);

    // ---- weight pre-pack (transposed) ----
    convwT_k<<<dim3(16384/32, 1024/64, 1), dim3(32,8)>>>(W_slot1, pWs1h, pWs1l, 16384, 1024);
    convwT_k<<<dim3(HID_/32, D_/64, E1_), dim3(32,8)>>>(W1_first, pW1fh, pW1fl, HID_, D_);
    convwT_k<<<dim3(D_/32, HID_/64, E1_), dim3(32,8)>>>(W2_first, pW2fh, pW2fl, D_, HID_);
    convwT_k<<<dim3(4096/32, 1024/64, 1), dim3(32,8)>>>(W_slot2, pWs2h, pWs2l, 4096, 1024);
    convwT_k<<<dim3(HID_/32, D_/64, E2_), dim3(32,8)>>>(W1_second, pW1sh, pW1sl, HID_, D_);
    convwT_k<<<dim3(D_/32, HID_/64, E2_), dim3(32,8)>>>(W2_second, pW2sh, pW2sl, D_, HID_);

    // ---- stage 1 ----
    token_scale_k<<<B_ * NTOK_, 256>>>(x);
    group_mean_k<<<BG_, 256>>>(x);
    gates_k<<<BG_, 256>>>(Wg, bg_bias);
    packrow_k<<<BG_ * D_ / 1024, 256>>>(p_gm, pgmH, pgmL);

    // se_raw = gm @ W_slot1
    tmma_k<0><<<dim3(16384/128, BG_/128, 1), 256>>>(
        pgmH, pgmL, pWs1h, pWs1l, p_se, nullptr, nullptr, nullptr,
        D_, 512, 512, 16384, 0, 0, 0, nullptr, 0, nullptr, nullptr);
    slot_norm_k<<<BG_ * M1_, 256>>>(gamma_slot1, gamma1);

    group_attn_k<<<BG_, 256>>>(x);

    // FFN1a: slots(packed) @ W1f -> h1 PACKED
    tmma_k<1><<<dim3(HID_/128, (BG_*S1_)/128, E1_), 256>>>(
        pslH, pslL, pW1fh, pW1fl, nullptr, nullptr, ph1H, ph1L,
        D_, 512, 512, HID_,
        (size_t)BG_*S1_*512, (size_t)HID_*512, (size_t)BG_*S1_*2048,
        b1_first, HID_, nullptr, nullptr);
    // FFN1b: h1(packed) @ W2f -> seq fp32 (gate scale + remap)
    tmma_k<2><<<dim3(D_/128, (BG_*S1_)/128, E1_), 256>>>(
        ph1H, ph1L, pW2fh, pW2fl, p_seq, nullptr, nullptr, nullptr,
        HID_, 2048, 2048, D_,
        (size_t)BG_*S1_*2048, (size_t)D_*2048, 0,
        b2_first, D_, p_gates, expert_g);

    // ---- stage 2 ----
    xs_norm_k<<<B_ * L2_, 256>>>(gamma2);
    cmean_k<<<B_ * N2_, 256>>>();
    packrow_k<<<(int)((size_t)B_ * L2_ * D_ / 1024), 256>>>(p_xs, pxsH, pxsL);
    packrow_k<<<B_ * N2_ * D_ / 1024, 256>>>(p_cmean, pcmH, pcmL);
    convwT_k<<<dim3(D_/32, L2_/64, B_), dim3(32,8)>>>(p_xs, pxsTH, pxsTL, D_, L2_);

    // se2_raw = cmean @ W_slot2 (scratch g_h1 fp32)
    tmma_k<0><<<dim3(4096/128, (B_*N2_)/128, 1), 256>>>(
        pcmH, pcmL, pWs2h, pWs2l, p_h1, nullptr, nullptr, nullptr,
        D_, 512, 512, 4096, 0, 0, 0, nullptr, 0, nullptr, nullptr);
    se2_normpack_k<<<B_ * N2_ * E2_, 256>>>(gamma_slot2, pse2H, pse2L);

    // logits2 = xs(packed) @ se2^T(packed); dual write (plain + staged transposed)
    tmma_k<5><<<dim3(L2_/128, L2_/128, B_), 256>>>(
        pxsH, pxsL, pse2H, pse2L, p_logits2, p_logits2T, nullptr, nullptr,
        D_, 512, 512, L2_,
        (size_t)L2_*512, (size_t)L2_*512, (size_t)L2_*L2_, nullptr, 0, nullptr, nullptr);

    rowsm_pack_k<<<B_ * L2_, 256>>>(p_logits2, pc2H, pc2L);
    rowsm_pack_k<<<B_ * L2_, 256>>>(p_logits2T, pdTH, pdTL);

    // slots2 = dispatchT @ xs -> expert-major PACKED
    tmma_k<4><<<dim3(D_/128, L2_/128, B_), 256>>>(
        pdTH, pdTL, pxsTH, pxsTL, nullptr, nullptr, ps2H, ps2L,
        L2_, 1024, 1024, D_,
        (size_t)L2_*1024, (size_t)D_*1024, 0, nullptr, 0, nullptr, nullptr);

    // FFN2a: slots2(packed) @ W1s -> h2 PACKED (reuse h1 arrays)
    tmma_k<1><<<dim3(HID_/128, (B_*N2_)/128, E2_), 256>>>(
        ps2H, ps2L, pW1sh, pW1sl, nullptr, nullptr, ph1H, ph1L,
        D_, 512, 512, HID_,
        (size_t)B_*N2_*512, (size_t)HID_*512, (size_t)B_*N2_*2048,
        b1_second, HID_, nullptr, nullptr);
    // FFN2b: h2(packed) @ W2s -> o2 fp32
    tmma_k<3><<<dim3(D_/128, (B_*N2_)/128, E2_), 256>>>(
        ph1H, ph1L, pW2sh, pW2sl, p_o2, nullptr, nullptr, nullptr,
        HID_, 2048, 2048, D_,
        (size_t)B_*N2_*2048, (size_t)D_*2048, 0,
        b2_second, D_, nullptr, nullptr);

    convwT_k<<<dim3(D_/32, L2_/64, B_), dim3(32,8)>>>(p_o2, po2TH, po2TL, D_, L2_);

    // out2 = comb2 @ o2 (both packed)
    tmma_k<0><<<dim3(D_/128, L2_/128, B_), 256>>>(
        pc2H, pc2L, po2TH, po2TL, p_out2, nullptr, nullptr, nullptr,
        L2_, 1024, 1024, D_,
        (size_t)L2_*1024, (size_t)D_*1024, (size_t)L2_*D_, nullptr, 0, nullptr, nullptr);

    final_k<<<BG_, 256>>>(out);
}

// round 16
// speedup vs baseline: 1.0796x; 1.0796x over previous
#include <cuda_runtime.h>
#include <cuda_bf16.h>
#include <math.h>
#include <stdint.h>

#define D_    1024
#define B_    4
#define NTOK_ 8192
#define KG    64
#define BG_   512
#define E1_   8
#define S1_   2
#define M1_   16
#define HID_  4096
#define E2_   4
#define L2_   2048
#define N2_   512

// ---------------- fp32 scratch ----------------
__device__ float g_gm[BG_*D_];
__device__ float g_gates[BG_];
__device__ float g_se[BG_*M1_*D_];
__device__ float g_combine[BG_*KG*M1_];
__device__ float g_slots[E1_*BG_*S1_*D_];
__device__ float g_h1[(size_t)E1_*BG_*S1_*HID_];
__device__ float g_seq[B_*L2_*D_];
__device__ float g_xs[B_*L2_*D_];
__device__ float g_cmean[B_*N2_*D_];
__device__ float g_logits2[(size_t)B_*L2_*L2_];
__device__ float g_logits2T[(size_t)B_*L2_*L2_];
__device__ float g_slots2[E2_*B_*N2_*D_];
__device__ float g_o2[B_*L2_*D_];
__device__ float g_out2[B_*L2_*D_];

// ---------------- pre-packed bf16 hi/lo weights, TRANSPOSED: H[n][k/2] ----------------
__device__ uint32_t g_Ws1h[(size_t)16384*512],      g_Ws1l[(size_t)16384*512];
__device__ uint32_t g_W1fh[(size_t)E1_*HID_*512],   g_W1fl[(size_t)E1_*HID_*512];
__device__ uint32_t g_W2fh[(size_t)E1_*D_*2048],    g_W2fl[(size_t)E1_*D_*2048];
__device__ uint32_t g_Ws2h[(size_t)4096*512],       g_Ws2l[(size_t)4096*512];
__device__ uint32_t g_W1sh[(size_t)E2_*HID_*512],   g_W1sl[(size_t)E2_*HID_*512];
__device__ uint32_t g_W2sh[(size_t)E2_*D_*2048],    g_W2sl[(size_t)E2_*D_*2048];

// ---------------- pre-packed activations ----------------
__device__ uint32_t g_se2H[(size_t)B_*L2_*512],   g_se2L[(size_t)B_*L2_*512];
__device__ uint32_t g_xsTH[(size_t)B_*D_*1024],   g_xsTL[(size_t)B_*D_*1024];
__device__ uint32_t g_o2TH[(size_t)B_*D_*1024],   g_o2TL[(size_t)B_*D_*1024];
__device__ uint32_t g_c2H[(size_t)B_*L2_*1024],   g_c2L[(size_t)B_*L2_*1024];
__device__ uint32_t g_dTH[(size_t)B_*L2_*1024],   g_dTL[(size_t)B_*L2_*1024];

// ---------------- helpers ----------------
__device__ __forceinline__ float gelu_exact(float x) {
    return 0.5f * x * (1.0f + erff(x * 0.70710678118654752440f));
}
__device__ __forceinline__ float blk_sum(float v, float* sm) {
    int t = threadIdx.x;
    sm[t] = v; __syncthreads();
    for (int s = 128; s > 0; s >>= 1) { if (t < s) sm[t] += sm[t + s]; __syncthreads(); }
    float r = sm[0]; __syncthreads(); return r;
}
__device__ __forceinline__ float blk_max(float v, float* sm) {
    int t = threadIdx.x;
    sm[t] = v; __syncthreads();
    for (int s = 128; s > 0; s >>= 1) { if (t < s) sm[t] = fmaxf(sm[t], sm[t + s]); __syncthreads(); }
    float r = sm[0]; __syncthreads(); return r;
}
__device__ __forceinline__ void packbf(float x, float y, uint32_t& h, uint32_t& l) {
    __nv_bfloat16 hx = __float2bfloat16(x), hy = __float2bfloat16(y);
    float rx = x - __bfloat162float(hx), ry = y - __bfloat162float(hy);
    h = ((uint32_t)__bfloat16_as_ushort(hy) << 16) | (uint32_t)__bfloat16_as_ushort(hx);
    l = ((uint32_t)__bfloat16_as_ushort(__float2bfloat16(ry)) << 16)
      | (uint32_t)__bfloat16_as_ushort(__float2bfloat16(rx));
}
__device__ __forceinline__ void mma16(float* c, const uint32_t* a, const uint32_t* b) {
    asm volatile(
        "mma.sync.aligned.m16n8k16.row.col.f32.bf16.bf16.f32 "
        "{%0,%1,%2,%3}, {%4,%5,%6,%7}, {%8,%9}, {%0,%1,%2,%3};"
        : "+f"(c[0]), "+f"(c[1]), "+f"(c[2]), "+f"(c[3])
        : "r"(a[0]), "r"(a[1]), "r"(a[2]), "r"(a[3]), "r"(b[0]), "r"(b[1]));
}
__device__ __forceinline__ void ldsm4(uint32_t& r0, uint32_t& r1, uint32_t& r2, uint32_t& r3,
                                      uint32_t addr) {
    asm volatile("ldmatrix.sync.aligned.m8n8.x4.shared.b16 {%0,%1,%2,%3}, [%4];"
                 : "=r"(r0), "=r"(r1), "=r"(r2), "=r"(r3) : "r"(addr));
}
__device__ __forceinline__ uint32_t smem_u32(const void* p) {
    uint32_t a;
    asm("{ .reg .u64 t; cvta.to.shared.u64 t, %1; cvt.u32.u64 %0, t; }" : "=r"(a) : "l"(p));
    return a;
}

// weight/act pre-pack TRANSPOSED: W[k][n] f32 -> H/L[n][k/2] packed bf16x2
__global__ void convwT_k(const float* __restrict__ W, uint32_t* __restrict__ H,
                         uint32_t* __restrict__ Lo, int N, int Kd) {
    __shared__ uint32_t th[32][33], tl[32][33];
    int Kd2 = Kd >> 1;
    size_t zW = (size_t)blockIdx.z * Kd * N;
    size_t zH = (size_t)blockIdx.z * (size_t)Kd2 * N;
    int n0 = blockIdx.x * 32, kp0 = blockIdx.y * 32;
    int tx = threadIdx.x, ty = threadIdx.y;
    #pragma unroll
    for (int r = 0; r < 4; r++) {
        int kpl = ty + 8 * r;
        int k = (kp0 + kpl) * 2;
        float v0 = W[zW + (size_t)k * N + n0 + tx];
        float v1 = W[zW + (size_t)(k + 1) * N + n0 + tx];
        packbf(v0, v1, th[kpl][tx], tl[kpl][tx]);
    }
    __syncthreads();
    #pragma unroll
    for (int r = 0; r < 4; r++) {
        int n = ty + 8 * r;
        size_t o = zH + (size_t)(n0 + n) * Kd2 + kp0 + tx;
        H[o] = th[tx][n];
        Lo[o] = tl[tx][n];
    }
}

// ---------------- small kernels ----------------
__global__ void group_mean_k(const float* __restrict__ x) {
    int bg = blockIdx.x;
    size_t base = (size_t)bg * KG * D_;
    for (int d = threadIdx.x; d < D_; d += 256) {
        float s = 0.f;
        for (int k = 0; k < KG; k++) s += x[base + (size_t)k * D_ + d];
        g_gm[(size_t)bg * D_ + d] = s * (1.0f / KG);
    }
}
__global__ void gates_k(const float* __restrict__ Wg, const float* __restrict__ bgb) {
    int bg = blockIdx.x;
    float s = 0.f;
    for (int d = threadIdx.x; d < D_; d += 256) s += g_gm[(size_t)bg * D_ + d] * Wg[d];
    __shared__ float sm[256];
    float tot = blk_sum(s, sm);
    if (threadIdx.x == 0) {
        float v = 1.0f / (1.0f + expf(-(tot + bgb[0])));
        g_gates[bg] = fminf(fmaxf(v, 0.01f), 1.0f);
    }
}
__global__ void slot_norm_k(const float* __restrict__ gs1, const float* __restrict__ g1) {
    int row = blockIdx.x;
    float* p = g_se + (size_t)row * D_;
    float ss = 0.f;
    for (int d = threadIdx.x; d < D_; d += 256) { float v = p[d]; ss += v * v; }
    __shared__ float sm[256];
    float tot = blk_sum(ss, sm);
    float sc = 32.0f / fmaxf(sqrtf(tot), 1e-8f);
    for (int d = threadIdx.x; d < D_; d += 256)
        p[d] = p[d] * sc * gs1[d] * g1[d];
}
__global__ void xs_norm_k(const float* __restrict__ g2) {
    int row = blockIdx.x;
    const float* p = g_seq + (size_t)row * D_;
    float ss = 0.f;
    for (int d = threadIdx.x; d < D_; d += 256) { float v = p[d]; ss += v * v; }
    __shared__ float sm[256];
    float tot = blk_sum(ss, sm);
    float sc = 32.0f / fmaxf(sqrtf(tot), 1e-8f);
    float* o = g_xs + (size_t)row * D_;
    for (int d = threadIdx.x; d < D_; d += 256)
        o[d] = p[d] * sc * g2[d];
}
__global__ void cmean_k() {
    int r = blockIdx.x;
    size_t base = (size_t)r * 4 * D_;
    for (int d = threadIdx.x; d < D_; d += 256) {
        float s = g_xs[base + d] + g_xs[base + D_ + d] + g_xs[base + 2*D_ + d] + g_xs[base + 3*D_ + d];
        g_cmean[(size_t)r * D_ + d] = s * 0.25f;
    }
}
// se2 norm, writes PACKED rows directly
__global__ void se2_normpack_k(const float* __restrict__ gs2,
                               uint32_t* __restrict__ H, uint32_t* __restrict__ L) {
    int bid = blockIdx.x;
    int r = bid >> 2, e = bid & 3;
    const float* in = g_h1 + (size_t)r * (E2_ * D_) + (size_t)e * D_;
    int t = threadIdx.x;
    float2 v0 = ((const float2*)in)[t];
    float2 v1 = ((const float2*)in)[t + 256];
    float ss = v0.x * v0.x + v0.y * v0.y + v1.x * v1.x + v1.y * v1.y;
    __shared__ float sm[256];
    float tot = blk_sum(ss, sm);
    float sc = 32.0f / fmaxf(sqrtf(tot), 1e-8f);
    int b = r >> 9, n = r & 511;
    size_t row = (size_t)b * L2_ + (size_t)e * N2_ + n;
    uint32_t h, l;
    packbf(v0.x * sc * gs2[2*t],     v0.y * sc * gs2[2*t+1],     h, l);
    H[row * 512 + t] = h; L[row * 512 + t] = l;
    packbf(v1.x * sc * gs2[2*t+512], v1.y * sc * gs2[2*t+513],   h, l);
    H[row * 512 + t + 256] = h; L[row * 512 + t + 256] = l;
}

// ---------------- fused group attention (token rmsnorm scale computed inline) ----------------
__global__ void __launch_bounds__(256) group_attn_k(const float* __restrict__ x) {
    int bg = blockIdx.x;
    int tid = threadIdx.x;
    __shared__ float xs_sm[64][65];
    __shared__ float se_sm[16][65];
    __shared__ float comb_sm[64][17];
    const float* xbase  = x + (size_t)bg * KG * D_;
    const float* sebase = g_se + (size_t)bg * M1_ * D_;
    int k = tid >> 2, q = tid & 3;
    float acc0 = 0.f, acc1 = 0.f, acc2 = 0.f, acc3 = 0.f;
    float ssq = 0.f;   // sum of squares of token k (all 4 q-threads compute identically)
    for (int c = 0; c < D_; c += 64) {
        #pragma unroll
        for (int i = 0; i < 4; i++) {
            int f = i * 256 + tid;
            int r = f >> 4, col = (f & 15) << 2;
            float4 v = *(const float4*)(xbase + (size_t)r * D_ + c + col);
            xs_sm[r][col] = v.x; xs_sm[r][col+1] = v.y; xs_sm[r][col+2] = v.z; xs_sm[r][col+3] = v.w;
        }
        {
            int r = tid >> 4, col = (tid & 15) << 2;
            float4 v = *(const float4*)(sebase + (size_t)r * D_ + c + col);
            se_sm[r][col] = v.x; se_sm[r][col+1] = v.y; se_sm[r][col+2] = v.z; se_sm[r][col+3] = v.w;
        }
        __syncthreads();
        #pragma unroll 8
        for (int dd = 0; dd < 64; dd++) {
            float xv = xs_sm[k][dd];
            ssq = fmaf(xv, xv, ssq);
            acc0 = fmaf(xv, se_sm[q*4+0][dd], acc0);
            acc1 = fmaf(xv, se_sm[q*4+1][dd], acc1);
            acc2 = fmaf(xv, se_sm[q*4+2][dd], acc2);
            acc3 = fmaf(xv, se_sm[q*4+3][dd], acc3);
        }
        __syncthreads();
    }
    float s1v = 32.0f / fmaxf(sqrtf(ssq), 1e-8f);
    acc0 *= s1v; acc1 *= s1v; acc2 *= s1v; acc3 *= s1v;
    float mx = fmaxf(fmaxf(acc0, acc1), fmaxf(acc2, acc3));
    mx = fmaxf(mx, __shfl_xor_sync(0xffffffffu, mx, 1));
    mx = fmaxf(mx, __shfl_xor_sync(0xffffffffu, mx, 2));
    float e0 = expf(acc0 - mx), e1 = expf(acc1 - mx), e2 = expf(acc2 - mx), e3 = expf(acc3 - mx);
    float s = e0 + e1 + e2 + e3;
    s += __shfl_xor_sync(0xffffffffu, s, 1);
    s += __shfl_xor_sync(0xffffffffu, s, 2);
    float inv = 1.0f / s;
    size_t cb = ((size_t)bg * KG + k) * M1_ + q * 4;
    comb_sm[k][q*4+0] = e0 * inv; g_combine[cb+0] = e0 * inv;
    comb_sm[k][q*4+1] = e1 * inv; g_combine[cb+1] = e1 * inv;
    comb_sm[k][q*4+2] = e2 * inv; g_combine[cb+2] = e2 * inv;
    comb_sm[k][q*4+3] = e3 * inv; g_combine[cb+3] = e3 * inv;
    __syncthreads();
    int m = tid >> 4, dq = tid & 15;
    for (int c = 0; c < D_; c += 64) {
        #pragma unroll
        for (int i = 0; i < 4; i++) {
            int f = i * 256 + tid;
            int r = f >> 4, col = (f & 15) << 2;
            float4 v = *(const float4*)(xbase + (size_t)r * D_ + c + col);
            xs_sm[r][col] = v.x; xs_sm[r][col+1] = v.y; xs_sm[r][col+2] = v.z; xs_sm[r][col+3] = v.w;
        }
        __syncthreads();
        float a0 = 0.f, a1 = 0.f, a2 = 0.f, a3 = 0.f;
        #pragma unroll 8
        for (int kk = 0; kk < 64; kk++) {
            float cv = comb_sm[kk][m];
            a0 = fmaf(cv, xs_sm[kk][dq*4+0], a0);
            a1 = fmaf(cv, xs_sm[kk][dq*4+1], a1);
            a2 = fmaf(cv, xs_sm[kk][dq*4+2], a2);
            a3 = fmaf(cv, xs_sm[kk][dq*4+3], a3);
        }
        int e = m >> 1, sl = m & 1;
        float4 vv; vv.x = a0; vv.y = a1; vv.z = a2; vv.w = a3;
        *(float4*)(g_slots + ((size_t)e * (BG_ * S1_) + bg * 2 + sl) * D_ + c + dq * 4) = vv;
        __syncthreads();
    }
}

// ======= bf16 split-3 tensor GEMM, 128x128 tile, Kc=16, ldmatrix, LDG+STS loaders, 2 CTAs/SM =======
// B ALWAYS pre-packed [N][K/2] hi/lo uint32.
// AM: 0 = A fp32 [M][K]; 2 = A pre-packed [M][K/2].
// EPI: 0 plain; 1 bias+gelu; 2 ffn1-out; 3 ffn2-out; 4 slots2 remap; 5 plain + transposed copy
template<int AM, int EPI>
__global__ void __launch_bounds__(256, 2) tmma_k(
    const float* __restrict__ A, const uint32_t* __restrict__ AH, const uint32_t* __restrict__ AL,
    const uint32_t* __restrict__ BH, const uint32_t* __restrict__ BL,
    float* __restrict__ C, float* __restrict__ C2,
    int Kd, int lda, int ldb, int ldc,
    size_t sA, size_t sB, size_t sC,
    const float* __restrict__ bias, int biasStride,
    const float* __restrict__ gvec, const float* __restrict__ evec)
{
    int z = blockIdx.z;
    if (AM == 0) A += (size_t)z * sA;
    else { AH += (size_t)z * sA; AL += (size_t)z * sA; }
    BH += (size_t)z * sB; BL += (size_t)z * sB;

    __shared__ uint32_t Ah[2][128][12];
    __shared__ uint32_t Al[2][128][12];
    __shared__ uint32_t Bh[2][128][12];
    __shared__ uint32_t Bl[2][128][12];

    int tid = threadIdx.x;
    int lane = tid & 31, wid = tid >> 5;
    int g = lane >> 2, tig = lane & 3;
    int wm = wid >> 2, wn = wid & 3;
    int m0 = blockIdx.y * 128, n0 = blockIdx.x * 128;

    uint32_t AhB = smem_u32(&Ah[0][0][0]);
    uint32_t AlB = smem_u32(&Al[0][0][0]);
    uint32_t BhB = smem_u32(&Bh[0][0][0]);
    uint32_t BlB = smem_u32(&Bl[0][0][0]);
    uint32_t aAdd = (uint32_t)(wm * 64 + (lane & 15)) * 48u + (uint32_t)(lane >> 4) * 16u;
    uint32_t bAdd = (uint32_t)(wn * 32 + (lane & 7) + ((lane >> 4) << 3)) * 48u
                  + (uint32_t)((lane >> 3) & 1) * 16u;

    float acc[4][4][4];
    #pragma unroll
    for (int i = 0; i < 4; i++)
        #pragma unroll
        for (int j = 0; j < 4; j++)
            #pragma unroll
            for (int r = 0; r < 4; r++) acc[i][j][r] = 0.f;

    int nChunks = Kd >> 4;
    float4 va0, va1;
    uint4 pah, pal, pbh, pbl;

    #define LOAD_CHUNK(k0) do {                                                                      \
        if (AM == 0) {                                                                               \
            const float* pa = A + (size_t)(m0 + (tid >> 1)) * lda + (k0) + (tid & 1) * 8;            \
            va0 = *(const float4*)pa; va1 = *(const float4*)(pa + 4);                                \
        } else {                                                                                     \
            size_t off = (size_t)(m0 + (tid >> 1)) * lda + ((k0) >> 1) + (tid & 1) * 4;              \
            pah = *(const uint4*)(AH + off); pal = *(const uint4*)(AL + off);                        \
        }                                                                                            \
        {                                                                                            \
            size_t off = (size_t)(n0 + (tid >> 1)) * ldb + ((k0) >> 1) + (tid & 1) * 4;              \
            pbh = *(const uint4*)(BH + off); pbl = *(const uint4*)(BL + off);                        \
        }                                                                                            \
    } while (0)

    #define STORE_CHUNK(buf) do {                                                                   \
        int mm = tid >> 1, w0 = (tid & 1) * 4;                                                       \
        if (AM == 0) {                                                                               \
            uint4 hq, lq;                                                                            \
            packbf(va0.x, va0.y, hq.x, lq.x); packbf(va0.z, va0.w, hq.y, lq.y);                      \
            packbf(va1.x, va1.y, hq.z, lq.z); packbf(va1.z, va1.w, hq.w, lq.w);                      \
            *(uint4*)&Ah[buf][mm][w0] = hq; *(uint4*)&Al[buf][mm][w0] = lq;                          \
        } else {                                                                                     \
            *(uint4*)&Ah[buf][mm][w0] = pah; *(uint4*)&Al[buf][mm][w0] = pal;                        \
        }                                                                                            \
        *(uint4*)&Bh[buf][mm][w0] = pbh; *(uint4*)&Bl[buf][mm][w0] = pbl;                            \
    } while (0)

    LOAD_CHUNK(0);
    STORE_CHUNK(0);
    __syncthreads();

    for (int t = 0; t < nChunks; t++) {
        int cur = t & 1;
        uint32_t cb = (uint32_t)cur * (128u * 48u);
        if (t + 1 < nChunks) LOAD_CHUNK((t + 1) * 16);

        uint32_t bh[4][2], bl[4][2];
        #pragma unroll
        for (int jj = 0; jj < 2; jj++) {
            ldsm4(bh[2*jj][0], bh[2*jj][1], bh[2*jj+1][0], bh[2*jj+1][1],
                  BhB + cb + bAdd + (uint32_t)jj * 16u * 48u);
            ldsm4(bl[2*jj][0], bl[2*jj][1], bl[2*jj+1][0], bl[2*jj+1][1],
                  BlB + cb + bAdd + (uint32_t)jj * 16u * 48u);
        }
        #pragma unroll
        for (int i = 0; i < 4; i++) {
            uint32_t ah[4], al[4];
            ldsm4(ah[0], ah[1], ah[2], ah[3], AhB + cb + aAdd + (uint32_t)i * 16u * 48u);
            ldsm4(al[0], al[1], al[2], al[3], AlB + cb + aAdd + (uint32_t)i * 16u * 48u);
            #pragma unroll
            for (int j = 0; j < 4; j++) {
                mma16(acc[i][j], al, bh[j]);
                mma16(acc[i][j], ah, bl[j]);
                mma16(acc[i][j], ah, bh[j]);
            }
        }

        if (t + 1 < nChunks) STORE_CHUNK((t + 1) & 1);
        __syncthreads();
    }
    #undef LOAD_CHUNK
    #undef STORE_CHUNK

    #pragma unroll
    for (int i = 0; i < 4; i++) {
        #pragma unroll
        for (int j = 0; j < 4; j++) {
            #pragma unroll
            for (int rr = 0; rr < 2; rr++) {
                int m = m0 + wm * 64 + 16 * i + g + rr * 8;
                int n = n0 + wn * 32 + 8 * j + 2 * tig;
                float v0 = acc[i][j][rr * 2 + 0];
                float v1 = acc[i][j][rr * 2 + 1];
                if (EPI == 0) {
                    float2 vv; vv.x = v0; vv.y = v1;
                    *(float2*)(C + (size_t)z * sC + (size_t)m * ldc + n) = vv;
                } else if (EPI == 1) {
                    v0 = gelu_exact(v0 + bias[(size_t)z * biasStride + n]);
                    v1 = gelu_exact(v1 + bias[(size_t)z * biasStride + n + 1]);
                    float2 vv; vv.x = v0; vv.y = v1;
                    *(float2*)(C + (size_t)z * sC + (size_t)m * ldc + n) = vv;
                } else if (EPI == 2) {
                    int e = z;
                    int row = (m >> 1) * M1_ + e * S1_ + (m & 1);
                    float sc = evec[e] * gvec[m >> 1];
                    float2 vv;
                    vv.x = (v0 + bias[(size_t)e * biasStride + n]) * sc;
                    vv.y = (v1 + bias[(size_t)e * biasStride + n + 1]) * sc;
                    *(float2*)(C + (size_t)row * ldc + n) = vv;
                } else if (EPI == 3) {
                    int e = z;
                    int row = (m >> 9) * L2_ + e * N2_ + (m & 511);
                    float2 vv;
                    vv.x = v0 + bias[(size_t)e * biasStride + n];
                    vv.y = v1 + bias[(size_t)e * biasStride + n + 1];
                    *(float2*)(C + (size_t)row * ldc + n) = vv;
                } else if (EPI == 4) {
                    int row = ((m >> 9) * B_ + z) * N2_ + (m & 511);
                    float2 vv; vv.x = v0; vv.y = v1;
                    *(float2*)(C + (size_t)row * ldc + n) = vv;
                } else { // EPI == 5: plain + transposed
                    float2 vv; vv.x = v0; vv.y = v1;
                    *(float2*)(C + (size_t)z * sC + (size_t)m * ldc + n) = vv;
                    float* t2 = C2 + (size_t)z * sC;
                    t2[(size_t)n * ldc + m] = v0;
                    t2[(size_t)(n + 1) * ldc + m] = v1;
                }
            }
        }
    }
}

// ---------------- row softmax with fused bf16 hi/lo pack output ----------------
__global__ void rowsm_pack_k(const float* __restrict__ src,
                             uint32_t* __restrict__ H, uint32_t* __restrict__ L) {
    int row = blockIdx.x;
    int t = threadIdx.x;
    const float2* p = (const float2*)(src + (size_t)row * L2_);
    float2 v[4];
    float mx = -1e30f;
    #pragma unroll
    for (int i = 0; i < 4; i++) {
        v[i] = p[i * 256 + t];
        mx = fmaxf(mx, fmaxf(v[i].x, v[i].y));
    }
    __shared__ float sm[256];
    mx = blk_max(mx, sm);
    float ex[4][2];
    float s = 0.f;
    #pragma unroll
    for (int i = 0; i < 4; i++) {
        ex[i][0] = expf(v[i].x - mx);
        ex[i][1] = expf(v[i].y - mx);
        s += ex[i][0] + ex[i][1];
    }
    s = blk_sum(s, sm);
    float inv = 1.0f / s;
    #pragma unroll
    for (int i = 0; i < 4; i++) {
        uint32_t h, l;
        packbf(ex[i][0] * inv, ex[i][1] * inv, h, l);
        H[(size_t)row * 1024 + i * 256 + t] = h;
        L[(size_t)row * 1024 + i * 256 + t] = l;
    }
}

// ---------------- final recombination ----------------
__global__ void __launch_bounds__(256) final_k(float* __restrict__ out) {
    int bg = blockIdx.x;
    int tid = threadIdx.x;
    __shared__ float comb[64 * 16];
    __shared__ float o2sm[16 * 256];
    #pragma unroll
    for (int i = 0; i < 4; i++)
        comb[i * 256 + tid] = g_combine[(size_t)bg * 1024 + i * 256 + tid];
    for (int c = 0; c < D_; c += 256) {
        __syncthreads();
        #pragma unroll
        for (int i = 0; i < 4; i++) {
            int f = i * 256 + tid;
            int r = f >> 6, col = (f & 63) << 2;
            *(float4*)&o2sm[r * 256 + col] =
                *(const float4*)(g_out2 + ((size_t)bg * M1_ + r) * D_ + c + col);
        }
        __syncthreads();
        for (int k = 0; k < 64; k++) {
            float s = 0.f;
            #pragma unroll
            for (int m = 0; m < 16; m++)
                s = fmaf(comb[k * 16 + m], o2sm[m * 256 + tid], s);
            out[((size_t)bg * KG + k) * D_ + c + tid] = s;
        }
    }
}

// ---------------- launch ----------------
extern "C" void kernel_launch(void* const* d_in, const int* in_sizes, int n_in,
                              void* d_out, int out_size) {
    const float* x           = (const float*)d_in[0];
    const float* gamma1      = (const float*)d_in[1];
    const float* W_slot1     = (const float*)d_in[2];
    const float* gamma_slot1 = (const float*)d_in[3];
    const float* W1_first    = (const float*)d_in[4];
    const float* b1_first    = (const float*)d_in[5];
    const float* W2_first    = (const float*)d_in[6];
    const float* b2_first    = (const float*)d_in[7];
    const float* expert_g    = (const float*)d_in[8];
    const float* Wg          = (const float*)d_in[9];
    const float* bg_bias     = (const float*)d_in[10];
    const float* gamma2      = (const float*)d_in[11];
    const float* W_slot2     = (const float*)d_in[12];
    const float* gamma_slot2 = (const float*)d_in[13];
    const float* W1_second   = (const float*)d_in[14];
    const float* b1_second   = (const float*)d_in[15];
    const float* W2_second   = (const float*)d_in[16];
    const float* b2_second   = (const float*)d_in[17];
    float* out = (float*)d_out;

    float *p_gm, *p_se, *p_slots, *p_h1, *p_seq, *p_xs, *p_cmean,
          *p_logits2, *p_logits2T, *p_slots2, *p_o2, *p_out2, *p_gates;
    uint32_t *pWs1h, *pWs1l, *pW1fh, *pW1fl, *pW2fh, *pW2fl,
             *pWs2h, *pWs2l, *pW1sh, *pW1sl, *pW2sh, *pW2sl;
    uint32_t *pse2H, *pse2L, *pxsTH, *pxsTL, *po2TH, *po2TL, *pc2H, *pc2L, *pdTH, *pdTL;
    cudaGetSymbolAddress((void**)&p_gm, g_gm);
    cudaGetSymbolAddress((void**)&p_gates, g_gates);
    cudaGetSymbolAddress((void**)&p_se, g_se);
    cudaGetSymbolAddress((void**)&p_slots, g_slots);
    cudaGetSymbolAddress((void**)&p_h1, g_h1);
    cudaGetSymbolAddress((void**)&p_seq, g_seq);
    cudaGetSymbolAddress((void**)&p_xs, g_xs);
    cudaGetSymbolAddress((void**)&p_cmean, g_cmean);
    cudaGetSymbolAddress((void**)&p_logits2, g_logits2);
    cudaGetSymbolAddress((void**)&p_logits2T, g_logits2T);
    cudaGetSymbolAddress((void**)&p_slots2, g_slots2);
    cudaGetSymbolAddress((void**)&p_o2, g_o2);
    cudaGetSymbolAddress((void**)&p_out2, g_out2);
    cudaGetSymbolAddress((void**)&pWs1h, g_Ws1h);
    cudaGetSymbolAddress((void**)&pWs1l, g_Ws1l);
    cudaGetSymbolAddress((void**)&pW1fh, g_W1fh);
    cudaGetSymbolAddress((void**)&pW1fl, g_W1fl);
    cudaGetSymbolAddress((void**)&pW2fh, g_W2fh);
    cudaGetSymbolAddress((void**)&pW2fl, g_W2fl);
    cudaGetSymbolAddress((void**)&pWs2h, g_Ws2h);
    cudaGetSymbolAddress((void**)&pWs2l, g_Ws2l);
    cudaGetSymbolAddress((void**)&pW1sh, g_W1sh);
    cudaGetSymbolAddress((void**)&pW1sl, g_W1sl);
    cudaGetSymbolAddress((void**)&pW2sh, g_W2sh);
    cudaGetSymbolAddress((void**)&pW2sl, g_W2sl);
    cudaGetSymbolAddress((void**)&pse2H, g_se2H);
    cudaGetSymbolAddress((void**)&pse2L, g_se2L);
    cudaGetSymbolAddress((void**)&pxsTH, g_xsTH);
    cudaGetSymbolAddress((void**)&pxsTL, g_xsTL);
    cudaGetSymbolAddress((void**)&po2TH, g_o2TH);
    cudaGetSymbolAddress((void**)&po2TL, g_o2TL);
    cudaGetSymbolAddress((void**)&pc2H, g_c2H);
    cudaGetSymbolAddress((void**)&pc2L, g_c2L);
    cudaGetSymbolAddress((void**)&pdTH, g_dTH);
    cudaGetSymbolAddress((void**)&pdTL, g_dTL);

    // ---- weight pre-pack (transposed) ----
    convwT_k<<<dim3(16384/32, 1024/64, 1), dim3(32,8)>>>(W_slot1, pWs1h, pWs1l, 16384, 1024);
    convwT_k<<<dim3(HID_/32, D_/64, E1_), dim3(32,8)>>>(W1_first, pW1fh, pW1fl, HID_, D_);
    convwT_k<<<dim3(D_/32, HID_/64, E1_), dim3(32,8)>>>(W2_first, pW2fh, pW2fl, D_, HID_);
    convwT_k<<<dim3(4096/32, 1024/64, 1), dim3(32,8)>>>(W_slot2, pWs2h, pWs2l, 4096, 1024);
    convwT_k<<<dim3(HID_/32, D_/64, E2_), dim3(32,8)>>>(W1_second, pW1sh, pW1sl, HID_, D_);
    convwT_k<<<dim3(D_/32, HID_/64, E2_), dim3(32,8)>>>(W2_second, pW2sh, pW2sl, D_, HID_);

    // ---- stage 1 ----
    group_mean_k<<<BG_, 256>>>(x);
    gates_k<<<BG_, 256>>>(Wg, bg_bias);

    tmma_k<0,0><<<dim3(16384/128, BG_/128, 1), 256>>>(
        p_gm, nullptr, nullptr, pWs1h, pWs1l, p_se, nullptr, D_, D_, 512, 16384,
        0, 0, 0, nullptr, 0, nullptr, nullptr);
    slot_norm_k<<<BG_ * M1_, 256>>>(gamma_slot1, gamma1);

    group_attn_k<<<BG_, 256>>>(x);

    tmma_k<0,1><<<dim3(HID_/128, (BG_*S1_)/128, E1_), 256>>>(
        p_slots, nullptr, nullptr, pW1fh, pW1fl, p_h1, nullptr, D_, D_, 512, HID_,
        (size_t)BG_*S1_*D_, (size_t)HID_*512, (size_t)BG_*S1_*HID_,
        b1_first, HID_, nullptr, nullptr);
    tmma_k<0,2><<<dim3(D_/128, (BG_*S1_)/128, E1_), 256>>>(
        p_h1, nullptr, nullptr, pW2fh, pW2fl, p_seq, nullptr, HID_, HID_, 2048, D_,
        (size_t)BG_*S1_*HID_, (size_t)D_*2048, 0,
        b2_first, D_, p_gates, expert_g);

    // ---- stage 2 ----
    xs_norm_k<<<B_ * L2_, 256>>>(gamma2);
    cmean_k<<<B_ * N2_, 256>>>();
    convwT_k<<<dim3(D_/32, L2_/64, B_), dim3(32,8)>>>(p_xs, pxsTH, pxsTL, D_, L2_);

    tmma_k<0,0><<<dim3(4096/128, (B_*N2_)/128, 1), 256>>>(
        p_cmean, nullptr, nullptr, pWs2h, pWs2l, p_h1, nullptr, D_, D_, 512, 4096,
        0, 0, 0, nullptr, 0, nullptr, nullptr);
    se2_normpack_k<<<B_ * N2_ * E2_, 256>>>(gamma_slot2, pse2H, pse2L);

    // logits2 = xs @ se2^T; dual write (plain + transposed)
    tmma_k<0,5><<<dim3(L2_/128, L2_/128, B_), 256>>>(
        p_xs, nullptr, nullptr, pse2H, pse2L, p_logits2, p_logits2T, D_, D_, 512, L2_,
        (size_t)L2_*D_, (size_t)L2_*512, (size_t)L2_*L2_, nullptr, 0, nullptr, nullptr);

    rowsm_pack_k<<<B_ * L2_, 256>>>(p_logits2, pc2H, pc2L);
    rowsm_pack_k<<<B_ * L2_, 256>>>(p_logits2T, pdTH, pdTL);

    // slots2 = dispatchT @ xs -> expert-major (both operands packed)
    tmma_k<2,4><<<dim3(D_/128, L2_/128, B_), 256>>>(
        nullptr, pdTH, pdTL, pxsTH, pxsTL, p_slots2, nullptr, L2_, 1024, 1024, D_,
        (size_t)L2_*1024, (size_t)D_*1024, 0, nullptr, 0, nullptr, nullptr);

    tmma_k<0,1><<<dim3(HID_/128, (B_*N2_)/128, E2_), 256>>>(
        p_slots2, nullptr, nullptr, pW1sh, pW1sl, p_h1, nullptr, D_, D_, 512, HID_,
        (size_t)B_*N2_*D_, (size_t)HID_*512, (size_t)B_*N2_*HID_,
        b1_second, HID_, nullptr, nullptr);
    tmma_k<0,3><<<dim3(D_/128, (B_*N2_)/128, E2_), 256>>>(
        p_h1, nullptr, nullptr, pW2sh, pW2sl, p_o2, nullptr, HID_, HID_, 2048, D_,
        (size_t)B_*N2_*HID_, (size_t)D_*2048, 0,
        b2_second, D_, nullptr, nullptr);

    convwT_k<<<dim3(D_/32, L2_/64, B_), dim3(32,8)>>>(p_o2, po2TH, po2TL, D_, L2_);

    // out2 = comb2 @ o2 (both operands packed)
    tmma_k<2,0><<<dim3(D_/128, L2_/128, B_), 256>>>(
        nullptr, pc2H, pc2L, po2TH, po2TL, p_out2, nullptr, L2_, 1024, 1024, D_,
        (size_t)L2_*1024, (size_t)D_*1024, (size_t)L2_*D_, nullptr, 0, nullptr, nullptr);

    final_k<<<BG_, 256>>>(out);
}

// round 17
// speedup vs baseline: 1.0815x; 1.0017x over previous
#include <cuda_runtime.h>
#include <cuda_bf16.h>
#include <math.h>
#include <stdint.h>

#define D_    1024
#define B_    4
#define NTOK_ 8192
#define KG    64
#define BG_   512
#define E1_   8
#define S1_   2
#define M1_   16
#define HID_  4096
#define E2_   4
#define L2_   2048
#define N2_   512

// ---------------- fp32 scratch ----------------
__device__ float g_gm[BG_*D_];
__device__ float g_gates[BG_];
__device__ float g_se[BG_*M1_*D_];
__device__ float g_combine[BG_*KG*M1_];
__device__ float g_slots[E1_*BG_*S1_*D_];
__device__ float g_h1[(size_t)E1_*BG_*S1_*HID_];
__device__ float g_seq[B_*L2_*D_];
__device__ float g_xs[B_*L2_*D_];
__device__ float g_cmean[B_*N2_*D_];
__device__ float g_logits2[(size_t)B_*L2_*L2_];
__device__ float g_logits2T[(size_t)B_*L2_*L2_];
__device__ float g_slots2[E2_*B_*N2_*D_];
__device__ float g_o2[B_*L2_*D_];
__device__ float g_out2[B_*L2_*D_];

// ---------------- pre-packed bf16 hi/lo weights, TRANSPOSED: H[n][k/2] ----------------
__device__ uint32_t g_Ws1h[(size_t)16384*512],      g_Ws1l[(size_t)16384*512];
__device__ uint32_t g_W1fh[(size_t)E1_*HID_*512],   g_W1fl[(size_t)E1_*HID_*512];
__device__ uint32_t g_W2fh[(size_t)E1_*D_*2048],    g_W2fl[(size_t)E1_*D_*2048];
__device__ uint32_t g_Ws2h[(size_t)4096*512],       g_Ws2l[(size_t)4096*512];
__device__ uint32_t g_W1sh[(size_t)E2_*HID_*512],   g_W1sl[(size_t)E2_*HID_*512];
__device__ uint32_t g_W2sh[(size_t)E2_*D_*2048],    g_W2sl[(size_t)E2_*D_*2048];

// ---------------- pre-packed activations ----------------
__device__ uint32_t g_se2H[(size_t)B_*L2_*512],   g_se2L[(size_t)B_*L2_*512];
__device__ uint32_t g_xsTH[(size_t)B_*D_*1024],   g_xsTL[(size_t)B_*D_*1024];
__device__ uint32_t g_o2TH[(size_t)B_*D_*1024],   g_o2TL[(size_t)B_*D_*1024];
__device__ uint32_t g_c2H[(size_t)B_*L2_*1024],   g_c2L[(size_t)B_*L2_*1024];
__device__ uint32_t g_dTH[(size_t)B_*L2_*1024],   g_dTL[(size_t)B_*L2_*1024];

// ---------------- helpers ----------------
__device__ __forceinline__ float gelu_exact(float x) {
    return 0.5f * x * (1.0f + erff(x * 0.70710678118654752440f));
}
__device__ __forceinline__ float blk_sum(float v, float* sm) {
    int t = threadIdx.x;
    sm[t] = v; __syncthreads();
    for (int s = 128; s > 0; s >>= 1) { if (t < s) sm[t] += sm[t + s]; __syncthreads(); }
    float r = sm[0]; __syncthreads(); return r;
}
__device__ __forceinline__ float blk_max(float v, float* sm) {
    int t = threadIdx.x;
    sm[t] = v; __syncthreads();
    for (int s = 128; s > 0; s >>= 1) { if (t < s) sm[t] = fmaxf(sm[t], sm[t + s]); __syncthreads(); }
    float r = sm[0]; __syncthreads(); return r;
}
__device__ __forceinline__ void packbf(float x, float y, uint32_t& h, uint32_t& l) {
    __nv_bfloat16 hx = __float2bfloat16(x), hy = __float2bfloat16(y);
    float rx = x - __bfloat162float(hx), ry = y - __bfloat162float(hy);
    h = ((uint32_t)__bfloat16_as_ushort(hy) << 16) | (uint32_t)__bfloat16_as_ushort(hx);
    l = ((uint32_t)__bfloat16_as_ushort(__float2bfloat16(ry)) << 16)
      | (uint32_t)__bfloat16_as_ushort(__float2bfloat16(rx));
}
__device__ __forceinline__ void mma16(float* c, const uint32_t* a, const uint32_t* b) {
    asm volatile(
        "mma.sync.aligned.m16n8k16.row.col.f32.bf16.bf16.f32 "
        "{%0,%1,%2,%3}, {%4,%5,%6,%7}, {%8,%9}, {%0,%1,%2,%3};"
        : "+f"(c[0]), "+f"(c[1]), "+f"(c[2]), "+f"(c[3])
        : "r"(a[0]), "r"(a[1]), "r"(a[2]), "r"(a[3]), "r"(b[0]), "r"(b[1]));
}
__device__ __forceinline__ void ldsm4(uint32_t& r0, uint32_t& r1, uint32_t& r2, uint32_t& r3,
                                      uint32_t addr) {
    asm volatile("ldmatrix.sync.aligned.m8n8.x4.shared.b16 {%0,%1,%2,%3}, [%4];"
                 : "=r"(r0), "=r"(r1), "=r"(r2), "=r"(r3) : "r"(addr));
}
__device__ __forceinline__ uint32_t smem_u32(const void* p) {
    uint32_t a;
    asm("{ .reg .u64 t; cvta.to.shared.u64 t, %1; cvt.u32.u64 %0, t; }" : "=r"(a) : "l"(p));
    return a;
}

// weight/act pre-pack TRANSPOSED: W[k][n] f32 -> H/L[n][k/2] packed bf16x2
__global__ void convwT_k(const float* __restrict__ W, uint32_t* __restrict__ H,
                         uint32_t* __restrict__ Lo, int N, int Kd) {
    __shared__ uint32_t th[32][33], tl[32][33];
    int Kd2 = Kd >> 1;
    size_t zW = (size_t)blockIdx.z * Kd * N;
    size_t zH = (size_t)blockIdx.z * (size_t)Kd2 * N;
    int n0 = blockIdx.x * 32, kp0 = blockIdx.y * 32;
    int tx = threadIdx.x, ty = threadIdx.y;
    #pragma unroll
    for (int r = 0; r < 4; r++) {
        int kpl = ty + 8 * r;
        int k = (kp0 + kpl) * 2;
        float v0 = W[zW + (size_t)k * N + n0 + tx];
        float v1 = W[zW + (size_t)(k + 1) * N + n0 + tx];
        packbf(v0, v1, th[kpl][tx], tl[kpl][tx]);
    }
    __syncthreads();
    #pragma unroll
    for (int r = 0; r < 4; r++) {
        int n = ty + 8 * r;
        size_t o = zH + (size_t)(n0 + n) * Kd2 + kp0 + tx;
        H[o] = th[tx][n];
        Lo[o] = tl[tx][n];
    }
}

// ---------------- small kernels ----------------
// group mean + gate (fused; same accumulation orders as the separate kernels)
__global__ void group_mean_gates_k(const float* __restrict__ x,
                                   const float* __restrict__ Wg,
                                   const float* __restrict__ bgb) {
    int bg = blockIdx.x;
    size_t base = (size_t)bg * KG * D_;
    float gd = 0.f;
    for (int d = threadIdx.x; d < D_; d += 256) {
        float s = 0.f;
        for (int k = 0; k < KG; k++) s += x[base + (size_t)k * D_ + d];
        float gm = s * (1.0f / KG);
        g_gm[(size_t)bg * D_ + d] = gm;
        gd += gm * Wg[d];
    }
    __shared__ float sm[256];
    float tot = blk_sum(gd, sm);
    if (threadIdx.x == 0) {
        float v = 1.0f / (1.0f + expf(-(tot + bgb[0])));
        g_gates[bg] = fminf(fmaxf(v, 0.01f), 1.0f);
    }
}
__global__ void slot_norm_k(const float* __restrict__ gs1, const float* __restrict__ g1) {
    int row = blockIdx.x;
    float* p = g_se + (size_t)row * D_;
    float ss = 0.f;
    for (int d = threadIdx.x; d < D_; d += 256) { float v = p[d]; ss += v * v; }
    __shared__ float sm[256];
    float tot = blk_sum(ss, sm);
    float sc = 32.0f / fmaxf(sqrtf(tot), 1e-8f);
    for (int d = threadIdx.x; d < D_; d += 256)
        p[d] = p[d] * sc * gs1[d] * g1[d];
}
// xs rmsnorm for 4 consecutive tokens + their consecutive-mean (fused cmean)
__global__ void xs_norm_cmean_k(const float* __restrict__ g2) {
    int r0 = blockIdx.x * 4;
    int t = threadIdx.x;
    __shared__ float sm[256];
    float sc[4];
    #pragma unroll
    for (int rr = 0; rr < 4; rr++) {
        const float* p = g_seq + (size_t)(r0 + rr) * D_;
        float ss = 0.f;
        for (int d = t; d < D_; d += 256) { float v = p[d]; ss += v * v; }
        float tot = blk_sum(ss, sm);
        sc[rr] = 32.0f / fmaxf(sqrtf(tot), 1e-8f);
    }
    for (int d = t; d < D_; d += 256) {
        float gv = g2[d];
        float x0 = g_seq[(size_t)(r0 + 0) * D_ + d] * sc[0] * gv;
        float x1 = g_seq[(size_t)(r0 + 1) * D_ + d] * sc[1] * gv;
        float x2 = g_seq[(size_t)(r0 + 2) * D_ + d] * sc[2] * gv;
        float x3 = g_seq[(size_t)(r0 + 3) * D_ + d] * sc[3] * gv;
        g_xs[(size_t)(r0 + 0) * D_ + d] = x0;
        g_xs[(size_t)(r0 + 1) * D_ + d] = x1;
        g_xs[(size_t)(r0 + 2) * D_ + d] = x2;
        g_xs[(size_t)(r0 + 3) * D_ + d] = x3;
        g_cmean[(size_t)blockIdx.x * D_ + d] = (x0 + x1 + x2 + x3) * 0.25f;
    }
}
// se2 norm, writes PACKED rows directly
__global__ void se2_normpack_k(const float* __restrict__ gs2,
                               uint32_t* __restrict__ H, uint32_t* __restrict__ L) {
    int bid = blockIdx.x;
    int r = bid >> 2, e = bid & 3;
    const float* in = g_h1 + (size_t)r * (E2_ * D_) + (size_t)e * D_;
    int t = threadIdx.x;
    float2 v0 = ((const float2*)in)[t];
    float2 v1 = ((const float2*)in)[t + 256];
    float ss = v0.x * v0.x + v0.y * v0.y + v1.x * v1.x + v1.y * v1.y;
    __shared__ float sm[256];
    float tot = blk_sum(ss, sm);
    float sc = 32.0f / fmaxf(sqrtf(tot), 1e-8f);
    int b = r >> 9, n = r & 511;
    size_t row = (size_t)b * L2_ + (size_t)e * N2_ + n;
    uint32_t h, l;
    packbf(v0.x * sc * gs2[2*t],     v0.y * sc * gs2[2*t+1],     h, l);
    H[row * 512 + t] = h; L[row * 512 + t] = l;
    packbf(v1.x * sc * gs2[2*t+512], v1.y * sc * gs2[2*t+513],   h, l);
    H[row * 512 + t + 256] = h; L[row * 512 + t + 256] = l;
}

// ---------------- fused group attention (token rmsnorm scale computed inline) ----------------
__global__ void __launch_bounds__(256) group_attn_k(const float* __restrict__ x) {
    int bg = blockIdx.x;
    int tid = threadIdx.x;
    __shared__ float xs_sm[64][65];
    __shared__ float se_sm[16][65];
    __shared__ float comb_sm[64][17];
    const float* xbase  = x + (size_t)bg * KG * D_;
    const float* sebase = g_se + (size_t)bg * M1_ * D_;
    int k = tid >> 2, q = tid & 3;
    float acc0 = 0.f, acc1 = 0.f, acc2 = 0.f, acc3 = 0.f;
    float ssq = 0.f;
    for (int c = 0; c < D_; c += 64) {
        #pragma unroll
        for (int i = 0; i < 4; i++) {
            int f = i * 256 + tid;
            int r = f >> 4, col = (f & 15) << 2;
            float4 v = *(const float4*)(xbase + (size_t)r * D_ + c + col);
            xs_sm[r][col] = v.x; xs_sm[r][col+1] = v.y; xs_sm[r][col+2] = v.z; xs_sm[r][col+3] = v.w;
        }
        {
            int r = tid >> 4, col = (tid & 15) << 2;
            float4 v = *(const float4*)(sebase + (size_t)r * D_ + c + col);
            se_sm[r][col] = v.x; se_sm[r][col+1] = v.y; se_sm[r][col+2] = v.z; se_sm[r][col+3] = v.w;
        }
        __syncthreads();
        #pragma unroll 8
        for (int dd = 0; dd < 64; dd++) {
            float xv = xs_sm[k][dd];
            ssq = fmaf(xv, xv, ssq);
            acc0 = fmaf(xv, se_sm[q*4+0][dd], acc0);
            acc1 = fmaf(xv, se_sm[q*4+1][dd], acc1);
            acc2 = fmaf(xv, se_sm[q*4+2][dd], acc2);
            acc3 = fmaf(xv, se_sm[q*4+3][dd], acc3);
        }
        __syncthreads();
    }
    float s1v = 32.0f / fmaxf(sqrtf(ssq), 1e-8f);
    acc0 *= s1v; acc1 *= s1v; acc2 *= s1v; acc3 *= s1v;
    float mx = fmaxf(fmaxf(acc0, acc1), fmaxf(acc2, acc3));
    mx = fmaxf(mx, __shfl_xor_sync(0xffffffffu, mx, 1));
    mx = fmaxf(mx, __shfl_xor_sync(0xffffffffu, mx, 2));
    float e0 = expf(acc0 - mx), e1 = expf(acc1 - mx), e2 = expf(acc2 - mx), e3 = expf(acc3 - mx);
    float s = e0 + e1 + e2 + e3;
    s += __shfl_xor_sync(0xffffffffu, s, 1);
    s += __shfl_xor_sync(0xffffffffu, s, 2);
    float inv = 1.0f / s;
    size_t cb = ((size_t)bg * KG + k) * M1_ + q * 4;
    comb_sm[k][q*4+0] = e0 * inv; g_combine[cb+0] = e0 * inv;
    comb_sm[k][q*4+1] = e1 * inv; g_combine[cb+1] = e1 * inv;
    comb_sm[k][q*4+2] = e2 * inv; g_combine[cb+2] = e2 * inv;
    comb_sm[k][q*4+3] = e3 * inv; g_combine[cb+3] = e3 * inv;
    __syncthreads();
    int m = tid >> 4, dq = tid & 15;
    for (int c = 0; c < D_; c += 64) {
        #pragma unroll
        for (int i = 0; i < 4; i++) {
            int f = i * 256 + tid;
            int r = f >> 4, col = (f & 15) << 2;
            float4 v = *(const float4*)(xbase + (size_t)r * D_ + c + col);
            xs_sm[r][col] = v.x; xs_sm[r][col+1] = v.y; xs_sm[r][col+2] = v.z; xs_sm[r][col+3] = v.w;
        }
        __syncthreads();
        float a0 = 0.f, a1 = 0.f, a2 = 0.f, a3 = 0.f;
        #pragma unroll 8
        for (int kk = 0; kk < 64; kk++) {
            float cv = comb_sm[kk][m];
            a0 = fmaf(cv, xs_sm[kk][dq*4+0], a0);
            a1 = fmaf(cv, xs_sm[kk][dq*4+1], a1);
            a2 = fmaf(cv, xs_sm[kk][dq*4+2], a2);
            a3 = fmaf(cv, xs_sm[kk][dq*4+3], a3);
        }
        int e = m >> 1, sl = m & 1;
        float4 vv; vv.x = a0; vv.y = a1; vv.z = a2; vv.w = a3;
        *(float4*)(g_slots + ((size_t)e * (BG_ * S1_) + bg * 2 + sl) * D_ + c + dq * 4) = vv;
        __syncthreads();
    }
}

// ======= bf16 split-3 tensor GEMM, 128x128 tile, Kc=16, ldmatrix, LDG+STS loaders, 2 CTAs/SM =======
// B ALWAYS pre-packed [N][K/2] hi/lo uint32.
// AM: 0 = A fp32 [M][K]; 2 = A pre-packed [M][K/2].
// EPI: 0 plain; 1 bias+gelu; 2 ffn1-out; 3 ffn2-out; 4 slots2 remap; 5 plain + transposed copy
template<int AM, int EPI>
__global__ void __launch_bounds__(256, 2) tmma_k(
    const float* __restrict__ A, const uint32_t* __restrict__ AH, const uint32_t* __restrict__ AL,
    const uint32_t* __restrict__ BH, const uint32_t* __restrict__ BL,
    float* __restrict__ C, float* __restrict__ C2,
    int Kd, int lda, int ldb, int ldc,
    size_t sA, size_t sB, size_t sC,
    const float* __restrict__ bias, int biasStride,
    const float* __restrict__ gvec, const float* __restrict__ evec)
{
    int z = blockIdx.z;
    if (AM == 0) A += (size_t)z * sA;
    else { AH += (size_t)z * sA; AL += (size_t)z * sA; }
    BH += (size_t)z * sB; BL += (size_t)z * sB;

    __shared__ uint32_t Ah[2][128][12];
    __shared__ uint32_t Al[2][128][12];
    __shared__ uint32_t Bh[2][128][12];
    __shared__ uint32_t Bl[2][128][12];

    int tid = threadIdx.x;
    int lane = tid & 31, wid = tid >> 5;
    int g = lane >> 2, tig = lane & 3;
    int wm = wid >> 2, wn = wid & 3;
    int m0 = blockIdx.y * 128, n0 = blockIdx.x * 128;

    uint32_t AhB = smem_u32(&Ah[0][0][0]);
    uint32_t AlB = smem_u32(&Al[0][0][0]);
    uint32_t BhB = smem_u32(&Bh[0][0][0]);
    uint32_t BlB = smem_u32(&Bl[0][0][0]);
    uint32_t aAdd = (uint32_t)(wm * 64 + (lane & 15)) * 48u + (uint32_t)(lane >> 4) * 16u;
    uint32_t bAdd = (uint32_t)(wn * 32 + (lane & 7) + ((lane >> 4) << 3)) * 48u
                  + (uint32_t)((lane >> 3) & 1) * 16u;

    float acc[4][4][4];
    #pragma unroll
    for (int i = 0; i < 4; i++)
        #pragma unroll
        for (int j = 0; j < 4; j++)
            #pragma unroll
            for (int r = 0; r < 4; r++) acc[i][j][r] = 0.f;

    int nChunks = Kd >> 4;
    float4 va0, va1;
    uint4 pah, pal, pbh, pbl;

    #define LOAD_CHUNK(k0) do {                                                                      \
        if (AM == 0) {                                                                               \
            const float* pa = A + (size_t)(m0 + (tid >> 1)) * lda + (k0) + (tid & 1) * 8;            \
            va0 = *(const float4*)pa; va1 = *(const float4*)(pa + 4);                                \
        } else {                                                                                     \
            size_t off = (size_t)(m0 + (tid >> 1)) * lda + ((k0) >> 1) + (tid & 1) * 4;              \
            pah = *(const uint4*)(AH + off); pal = *(const uint4*)(AL + off);                        \
        }                                                                                            \
        {                                                                                            \
            size_t off = (size_t)(n0 + (tid >> 1)) * ldb + ((k0) >> 1) + (tid & 1) * 4;              \
            pbh = *(const uint4*)(BH + off); pbl = *(const uint4*)(BL + off);                        \
        }                                                                                            \
    } while (0)

    #define STORE_CHUNK(buf) do {                                                                   \
        int mm = tid >> 1, w0 = (tid & 1) * 4;                                                       \
        if (AM == 0) {                                                                               \
            uint4 hq, lq;                                                                            \
            packbf(va0.x, va0.y, hq.x, lq.x); packbf(va0.z, va0.w, hq.y, lq.y);                      \
            packbf(va1.x, va1.y, hq.z, lq.z); packbf(va1.z, va1.w, hq.w, lq.w);                      \
            *(uint4*)&Ah[buf][mm][w0] = hq; *(uint4*)&Al[buf][mm][w0] = lq;                          \
        } else {                                                                                     \
            *(uint4*)&Ah[buf][mm][w0] = pah; *(uint4*)&Al[buf][mm][w0] = pal;                        \
        }                                                                                            \
        *(uint4*)&Bh[buf][mm][w0] = pbh; *(uint4*)&Bl[buf][mm][w0] = pbl;                            \
    } while (0)

    LOAD_CHUNK(0);
    STORE_CHUNK(0);
    __syncthreads();

    for (int t = 0; t < nChunks; t++) {
        int cur = t & 1;
        uint32_t cb = (uint32_t)cur * (128u * 48u);
        if (t + 1 < nChunks) LOAD_CHUNK((t + 1) * 16);

        uint32_t bh[4][2], bl[4][2];
        #pragma unroll
        for (int jj = 0; jj < 2; jj++) {
            ldsm4(bh[2*jj][0], bh[2*jj][1], bh[2*jj+1][0], bh[2*jj+1][1],
                  BhB + cb + bAdd + (uint32_t)jj * 16u * 48u);
            ldsm4(bl[2*jj][0], bl[2*jj][1], bl[2*jj+1][0], bl[2*jj+1][1],
                  BlB + cb + bAdd + (uint32_t)jj * 16u * 48u);
        }
        #pragma unroll
        for (int i = 0; i < 4; i++) {
            uint32_t ah[4], al[4];
            ldsm4(ah[0], ah[1], ah[2], ah[3], AhB + cb + aAdd + (uint32_t)i * 16u * 48u);
            ldsm4(al[0], al[1], al[2], al[3], AlB + cb + aAdd + (uint32_t)i * 16u * 48u);
            #pragma unroll
            for (int j = 0; j < 4; j++) {
                mma16(acc[i][j], al, bh[j]);
                mma16(acc[i][j], ah, bl[j]);
                mma16(acc[i][j], ah, bh[j]);
            }
        }

        if (t + 1 < nChunks) STORE_CHUNK((t + 1) & 1);
        __syncthreads();
    }
    #undef LOAD_CHUNK
    #undef STORE_CHUNK

    #pragma unroll
    for (int i = 0; i < 4; i++) {
        #pragma unroll
        for (int j = 0; j < 4; j++) {
            #pragma unroll
            for (int rr = 0; rr < 2; rr++) {
                int m = m0 + wm * 64 + 16 * i + g + rr * 8;
                int n = n0 + wn * 32 + 8 * j + 2 * tig;
                float v0 = acc[i][j][rr * 2 + 0];
                float v1 = acc[i][j][rr * 2 + 1];
                if (EPI == 0) {
                    float2 vv; vv.x = v0; vv.y = v1;
                    *(float2*)(C + (size_t)z * sC + (size_t)m * ldc + n) = vv;
                } else if (EPI == 1) {
                    v0 = gelu_exact(v0 + bias[(size_t)z * biasStride + n]);
                    v1 = gelu_exact(v1 + bias[(size_t)z * biasStride + n + 1]);
                    float2 vv; vv.x = v0; vv.y = v1;
                    *(float2*)(C + (size_t)z * sC + (size_t)m * ldc + n) = vv;
                } else if (EPI == 2) {
                    int e = z;
                    int row = (m >> 1) * M1_ + e * S1_ + (m & 1);
                    float sc = evec[e] * gvec[m >> 1];
                    float2 vv;
                    vv.x = (v0 + bias[(size_t)e * biasStride + n]) * sc;
                    vv.y = (v1 + bias[(size_t)e * biasStride + n + 1]) * sc;
                    *(float2*)(C + (size_t)row * ldc + n) = vv;
                } else if (EPI == 3) {
                    int e = z;
                    int row = (m >> 9) * L2_ + e * N2_ + (m & 511);
                    float2 vv;
                    vv.x = v0 + bias[(size_t)e * biasStride + n];
                    vv.y = v1 + bias[(size_t)e * biasStride + n + 1];
                    *(float2*)(C + (size_t)row * ldc + n) = vv;
                } else if (EPI == 4) {
                    int row = ((m >> 9) * B_ + z) * N2_ + (m & 511);
                    float2 vv; vv.x = v0; vv.y = v1;
                    *(float2*)(C + (size_t)row * ldc + n) = vv;
                } else { // EPI == 5: plain + transposed
                    float2 vv; vv.x = v0; vv.y = v1;
                    *(float2*)(C + (size_t)z * sC + (size_t)m * ldc + n) = vv;
                    float* t2 = C2 + (size_t)z * sC;
                    t2[(size_t)n * ldc + m] = v0;
                    t2[(size_t)(n + 1) * ldc + m] = v1;
                }
            }
        }
    }
}

// ---------------- row softmax with fused bf16 hi/lo pack output ----------------
__global__ void rowsm_pack_k(const float* __restrict__ src,
                             uint32_t* __restrict__ H, uint32_t* __restrict__ L) {
    int row = blockIdx.x;
    int t = threadIdx.x;
    const float2* p = (const float2*)(src + (size_t)row * L2_);
    float2 v[4];
    float mx = -1e30f;
    #pragma unroll
    for (int i = 0; i < 4; i++) {
        v[i] = p[i * 256 + t];
        mx = fmaxf(mx, fmaxf(v[i].x, v[i].y));
    }
    __shared__ float sm[256];
    mx = blk_max(mx, sm);
    float ex[4][2];
    float s = 0.f;
    #pragma unroll
    for (int i = 0; i < 4; i++) {
        ex[i][0] = expf(v[i].x - mx);
        ex[i][1] = expf(v[i].y - mx);
        s += ex[i][0] + ex[i][1];
    }
    s = blk_sum(s, sm);
    float inv = 1.0f / s;
    #pragma unroll
    for (int i = 0; i < 4; i++) {
        uint32_t h, l;
        packbf(ex[i][0] * inv, ex[i][1] * inv, h, l);
        H[(size_t)row * 1024 + i * 256 + t] = h;
        L[(size_t)row * 1024 + i * 256 + t] = l;
    }
}

// ---------------- final recombination ----------------
__global__ void __launch_bounds__(256) final_k(float* __restrict__ out) {
    int bg = blockIdx.x;
    int tid = threadIdx.x;
    __shared__ float comb[64 * 16];
    __shared__ float o2sm[16 * 256];
    #pragma unroll
    for (int i = 0; i < 4; i++)
        comb[i * 256 + tid] = g_combine[(size_t)bg * 1024 + i * 256 + tid];
    for (int c = 0; c < D_; c += 256) {
        __syncthreads();
        #pragma unroll
        for (int i = 0; i < 4; i++) {
            int f = i * 256 + tid;
            int r = f >> 6, col = (f & 63) << 2;
            *(float4*)&o2sm[r * 256 + col] =
                *(const float4*)(g_out2 + ((size_t)bg * M1_ + r) * D_ + c + col);
        }
        __syncthreads();
        for (int k = 0; k < 64; k++) {
            float s = 0.f;
            #pragma unroll
            for (int m = 0; m < 16; m++)
                s = fmaf(comb[k * 16 + m], o2sm[m * 256 + tid], s);
            out[((size_t)bg * KG + k) * D_ + c + tid] = s;
        }
    }
}

// ---------------- launch ----------------
extern "C" void kernel_launch(void* const* d_in, const int* in_sizes, int n_in,
                              void* d_out, int out_size) {
    const float* x           = (const float*)d_in[0];
    const float* gamma1      = (const float*)d_in[1];
    const float* W_slot1     = (const float*)d_in[2];
    const float* gamma_slot1 = (const float*)d_in[3];
    const float* W1_first    = (const float*)d_in[4];
    const float* b1_first    = (const float*)d_in[5];
    const float* W2_first    = (const float*)d_in[6];
    const float* b2_first    = (const float*)d_in[7];
    const float* expert_g    = (const float*)d_in[8];
    const float* Wg          = (const float*)d_in[9];
    const float* bg_bias     = (const float*)d_in[10];
    const float* gamma2      = (const float*)d_in[11];
    const float* W_slot2     = (const float*)d_in[12];
    const float* gamma_slot2 = (const float*)d_in[13];
    const float* W1_second   = (const float*)d_in[14];
    const float* b1_second   = (const float*)d_in[15];
    const float* W2_second   = (const float*)d_in[16];
    const float* b2_second   = (const float*)d_in[17];
    float* out = (float*)d_out;

    float *p_gm, *p_se, *p_slots, *p_h1, *p_seq, *p_xs, *p_cmean,
          *p_logits2, *p_logits2T, *p_slots2, *p_o2, *p_out2, *p_gates;
    uint32_t *pWs1h, *pWs1l, *pW1fh, *pW1fl, *pW2fh, *pW2fl,
             *pWs2h, *pWs2l, *pW1sh, *pW1sl, *pW2sh, *pW2sl;
    uint32_t *pse2H, *pse2L, *pxsTH, *pxsTL, *po2TH, *po2TL, *pc2H, *pc2L, *pdTH, *pdTL;
    cudaGetSymbolAddress((void**)&p_gm, g_gm);
    cudaGetSymbolAddress((void**)&p_gates, g_gates);
    cudaGetSymbolAddress((void**)&p_se, g_se);
    cudaGetSymbolAddress((void**)&p_slots, g_slots);
    cudaGetSymbolAddress((void**)&p_h1, g_h1);
    cudaGetSymbolAddress((void**)&p_seq, g_seq);
    cudaGetSymbolAddress((void**)&p_xs, g_xs);
    cudaGetSymbolAddress((void**)&p_cmean, g_cmean);
    cudaGetSymbolAddress((void**)&p_logits2, g_logits2);
    cudaGetSymbolAddress((void**)&p_logits2T, g_logits2T);
    cudaGetSymbolAddress((void**)&p_slots2, g_slots2);
    cudaGetSymbolAddress((void**)&p_o2, g_o2);
    cudaGetSymbolAddress((void**)&p_out2, g_out2);
    cudaGetSymbolAddress((void**)&pWs1h, g_Ws1h);
    cudaGetSymbolAddress((void**)&pWs1l, g_Ws1l);
    cudaGetSymbolAddress((void**)&pW1fh, g_W1fh);
    cudaGetSymbolAddress((void**)&pW1fl, g_W1fl);
    cudaGetSymbolAddress((void**)&pW2fh, g_W2fh);
    cudaGetSymbolAddress((void**)&pW2fl, g_W2fl);
    cudaGetSymbolAddress((void**)&pWs2h, g_Ws2h);
    cudaGetSymbolAddress((void**)&pWs2l, g_Ws2l);
    cudaGetSymbolAddress((void**)&pW1sh, g_W1sh);
    cudaGetSymbolAddress((void**)&pW1sl, g_W1sl);
    cudaGetSymbolAddress((void**)&pW2sh, g_W2sh);
    cudaGetSymbolAddress((void**)&pW2sl, g_W2sl);
    cudaGetSymbolAddress((void**)&pse2H, g_se2H);
    cudaGetSymbolAddress((void**)&pse2L, g_se2L);
    cudaGetSymbolAddress((void**)&pxsTH, g_xsTH);
    cudaGetSymbolAddress((void**)&pxsTL, g_xsTL);
    cudaGetSymbolAddress((void**)&po2TH, g_o2TH);
    cudaGetSymbolAddress((void**)&po2TL, g_o2TL);
    cudaGetSymbolAddress((void**)&pc2H, g_c2H);
    cudaGetSymbolAddress((void**)&pc2L, g_c2L);
    cudaGetSymbolAddress((void**)&pdTH, g_dTH);
    cudaGetSymbolAddress((void**)&pdTL, g_dTL);

    // ---- weight pre-pack (transposed) ----
    convwT_k<<<dim3(16384/32, 1024/64, 1), dim3(32,8)>>>(W_slot1, pWs1h, pWs1l, 16384, 1024);
    convwT_k<<<dim3(HID_/32, D_/64, E1_), dim3(32,8)>>>(W1_first, pW1fh, pW1fl, HID_, D_);
    convwT_k<<<dim3(D_/32, HID_/64, E1_), dim3(32,8)>>>(W2_first, pW2fh, pW2fl, D_, HID_);
    convwT_k<<<dim3(4096/32, 1024/64, 1), dim3(32,8)>>>(W_slot2, pWs2h, pWs2l, 4096, 1024);
    convwT_k<<<dim3(HID_/32, D_/64, E2_), dim3(32,8)>>>(W1_second, pW1sh, pW1sl, HID_, D_);
    convwT_k<<<dim3(D_/32, HID_/64, E2_), dim3(32,8)>>>(W2_second, pW2sh, pW2sl, D_, HID_);

    // ---- stage 1 ----
    group_mean_gates_k<<<BG_, 256>>>(x, Wg, bg_bias);

    tmma_k<0,0><<<dim3(16384/128, BG_/128, 1), 256>>>(
        p_gm, nullptr, nullptr, pWs1h, pWs1l, p_se, nullptr, D_, D_, 512, 16384,
        0, 0, 0, nullptr, 0, nullptr, nullptr);
    slot_norm_k<<<BG_ * M1_, 256>>>(gamma_slot1, gamma1);

    group_attn_k<<<BG_, 256>>>(x);

    tmma_k<0,1><<<dim3(HID_/128, (BG_*S1_)/128, E1_), 256>>>(
        p_slots, nullptr, nullptr, pW1fh, pW1fl, p_h1, nullptr, D_, D_, 512, HID_,
        (size_t)BG_*S1_*D_, (size_t)HID_*512, (size_t)BG_*S1_*HID_,
        b1_first, HID_, nullptr, nullptr);
    tmma_k<0,2><<<dim3(D_/128, (BG_*S1_)/128, E1_), 256>>>(
        p_h1, nullptr, nullptr, pW2fh, pW2fl, p_seq, nullptr, HID_, HID_, 2048, D_,
        (size_t)BG_*S1_*HID_, (size_t)D_*2048, 0,
        b2_first, D_, p_gates, expert_g);

    // ---- stage 2 ----
    xs_norm_cmean_k<<<B_ * N2_, 256>>>(gamma2);
    convwT_k<<<dim3(D_/32, L2_/64, B_), dim3(32,8)>>>(p_xs, pxsTH, pxsTL, D_, L2_);

    tmma_k<0,0><<<dim3(4096/128, (B_*N2_)/128, 1), 256>>>(
        p_cmean, nullptr, nullptr, pWs2h, pWs2l, p_h1, nullptr, D_, D_, 512, 4096,
        0, 0, 0, nullptr, 0, nullptr, nullptr);
    se2_normpack_k<<<B_ * N2_ * E2_, 256>>>(gamma_slot2, pse2H, pse2L);

    // logits2 = xs @ se2^T; dual write (plain + transposed)
    tmma_k<0,5><<<dim3(L2_/128, L2_/128, B_), 256>>>(
        p_xs, nullptr, nullptr, pse2H, pse2L, p_logits2, p_logits2T, D_, D_, 512, L2_,
        (size_t)L2_*D_, (size_t)L2_*512, (size_t)L2_*L2_, nullptr, 0, nullptr, nullptr);

    rowsm_pack_k<<<B_ * L2_, 256>>>(p_logits2, pc2H, pc2L);
    rowsm_pack_k<<<B_ * L2_, 256>>>(p_logits2T, pdTH, pdTL);

    // slots2 = dispatchT @ xs -> expert-major (both operands packed)
    tmma_k<2,4><<<dim3(D_/128, L2_/128, B_), 256>>>(
        nullptr, pdTH, pdTL, pxsTH, pxsTL, p_slots2, nullptr, L2_, 1024, 1024, D_,
        (size_t)L2_*1024, (size_t)D_*1024, 0, nullptr, 0, nullptr, nullptr);

    tmma_k<0,1><<<dim3(HID_/128, (B_*N2_)/128, E2_), 256>>>(
        p_slots2, nullptr, nullptr, pW1sh, pW1sl, p_h1, nullptr, D_, D_, 512, HID_,
        (size_t)B_*N2_*D_, (size_t)HID_*512, (size_t)B_*N2_*HID_,
        b1_second, HID_, nullptr, nullptr);
    tmma_k<0,3><<<dim3(D_/128, (B_*N2_)/128, E2_), 256>>>(
        p_h1, nullptr, nullptr, pW2sh, pW2sl, p_o2, nullptr, HID_, HID_, 2048, D_,
        (size_t)B_*N2_*HID_, (size_t)D_*2048, 0,
        b2_second, D_, nullptr, nullptr);

    convwT_k<<<dim3(D_/32, L2_/64, B_), dim3(32,8)>>>(p_o2, po2TH, po2TL, D_, L2_);

    // out2 = comb2 @ o2 (both operands packed)
    tmma_k<2,0><<<dim3(D_/128, L2_/128, B_), 256>>>(
        nullptr, pc2H, pc2L, po2TH, po2TL, p_out2, nullptr, L2_, 1024, 1024, D_,
        (size_t)L2_*1024, (size_t)D_*1024, (size_t)L2_*D_, nullptr, 0, nullptr, nullptr);

    final_k<<<BG_, 256>>>(out);
}